// round 1
// baseline (speedup 1.0000x reference)
#include <cuda_runtime.h>

#define N_E 384
#define HIDN 128
#define NHD 8
#define DHD 16
#define NRB 64

typedef unsigned long long ull;

// ---------------- scratch (no allocations allowed) ----------------
__device__ float g_q[N_E * HIDN];
__device__ float g_k[N_E * HIDN];
__device__ float g_v[N_E * HIDN];
__device__ float g_qc[N_E * NHD * HIDN];
__device__ float g_kc[N_E * NHD * HIDN];
__device__ float g_gate[N_E * NHD];
__device__ float g_scores[NHD * N_E * N_E];
__device__ float g_upd[N_E * HIDN];

// ---------------- helpers ----------------
__device__ __forceinline__ float silu_f(float x) {
    // x * sigmoid(x) = x / (1 + e^-x)
    return __fdividef(x, 1.0f + __expf(-x));
}
__device__ __forceinline__ float wsum(float v) {
#pragma unroll
    for (int o = 16; o; o >>= 1) v += __shfl_xor_sync(0xffffffffu, v, o);
    return v;
}
__device__ __forceinline__ float wmax(float v) {
#pragma unroll
    for (int o = 16; o; o >>= 1) v = fmaxf(v, __shfl_xor_sync(0xffffffffu, v, o));
    return v;
}
__device__ __forceinline__ ull pack2(float lo, float hi) {
    ull r;
    asm("mov.b64 %0, {%1, %2};" : "=l"(r) : "f"(lo), "f"(hi));
    return r;
}
__device__ __forceinline__ void unpack2(ull v, float& lo, float& hi) {
    asm("mov.b64 {%0, %1}, %2;" : "=f"(lo), "=f"(hi) : "l"(v));
}
__device__ __forceinline__ void fma2(ull& d, ull a, ull b) {
    asm("fma.rn.f32x2 %0, %1, %2, %0;" : "+l"(d) : "l"(a), "l"(b));
}

// ---------------- kernel 1: q,k,v projections ----------------
__global__ void k_qkv(const float* __restrict__ ef, const float* __restrict__ wq,
                      const float* __restrict__ wk, const float* __restrict__ wv) {
    int i = blockIdx.x, t = threadIdx.x;
    __shared__ float s_e[HIDN];
    s_e[t] = ef[i * HIDN + t];
    __syncthreads();
    float aq = 0.f, ak = 0.f, av = 0.f;
#pragma unroll 4
    for (int c = 0; c < HIDN; c++) {
        float e = s_e[c];
        aq += e * wq[c * HIDN + t];
        ak += e * wk[c * HIDN + t];
        av += e * wv[c * HIDN + t];
    }
    g_q[i * HIDN + t] = aq;
    g_k[i * HIDN + t] = ak;
    g_v[i * HIDN + t] = av;
}

// ---------------- kernel 2: qc = q@a_w1[0:16], kc = k@a_w1[16:32] ----------------
__global__ void k_qckc(const float* __restrict__ aw1) {
    int i = blockIdx.x, h = blockIdx.y, t = threadIdx.x;
    const float* qr = g_q + i * HIDN + h * DHD;
    const float* kr = g_k + i * HIDN + h * DHD;
    float aq = 0.f, ak = 0.f;
#pragma unroll
    for (int d = 0; d < DHD; d++) {
        aq += qr[d] * aw1[d * HIDN + t];
        ak += kr[d] * aw1[(DHD + d) * HIDN + t];
    }
    g_qc[(i * NHD + h) * HIDN + t] = aq;
    g_kc[(i * NHD + h) * HIDN + t] = ak;
}

// ---------------- kernel 3: gates (indexed by query row i) ----------------
__global__ void k_gate(const float* __restrict__ gw1, const float* __restrict__ gb1,
                       const float* __restrict__ gw2, const float* __restrict__ gb2) {
    int i = blockIdx.x, h = blockIdx.y, t = threadIdx.x;
    int lane = t & 31, wid = t >> 5;
    const float* vr = g_v + i * HIDN + h * DHD;
    float acc = gb1[t];
#pragma unroll
    for (int d = 0; d < DHD; d++) acc += vr[d] * gw1[d * HIDN + t];
    float p = silu_f(acc) * gw2[t];
    p = wsum(p);
    __shared__ float sr[4];
    if (lane == 0) sr[wid] = p;
    __syncthreads();
    if (t == 0) {
        float s = sr[0] + sr[1] + sr[2] + sr[3] + gb2[0];
        g_gate[i * NHD + h] = __fdividef(1.0f, 1.0f + __expf(-s));
    }
}

// ---------------- kernel 4: per-pair MLP -> scores ----------------
// smem layout (floats): w2[16384] | w1r[8320] | x1[8192] | qc[1024] | rbf[512] | dot[8] | dist[8]
#define K4_SMEM_FLOATS (16384 + 8320 + 8192 + 1024 + 512 + 8 + 8)
#define K4_SMEM_BYTES (K4_SMEM_FLOATS * 4)

__global__ void __launch_bounds__(256, 1)
k_pair(const float* __restrict__ ec, const float* __restrict__ rc,
       const float* __restrict__ rw, const float* __restrict__ aw1,
       const float* __restrict__ ab1, const float* __restrict__ aw2,
       const float* __restrict__ ab2, const float* __restrict__ aw3,
       const float* __restrict__ ab3, const float* __restrict__ mask) {
    extern __shared__ float sm[];
    float* s_w2 = sm;                 // [cin*128 + cout]
    float* s_w1r = s_w2 + 16384;      // a_w1 rows 32..96
    float* s_x1 = s_w1r + 8320;       // [h][cin][pair] : h*1024 + cin*8 + p
    float* s_qc = s_x1 + 8192;        // [h][c]
    float* s_rbf = s_qc + 1024;       // [p][r]
    float* s_dot = s_rbf + 512;
    float* s_dist = s_dot + 8;

    int i = blockIdx.x;
    int j0 = blockIdx.y * 8;
    int tid = threadIdx.x, lane = tid & 31, warp = tid >> 5;

    for (int idx = tid; idx < 16384; idx += 256) s_w2[idx] = aw2[idx];
    for (int idx = tid; idx < 8320; idx += 256) s_w1r[idx] = aw1[32 * HIDN + idx];
    for (int idx = tid; idx < 1024; idx += 256) s_qc[idx] = g_qc[i * 1024 + idx];

    if (tid < 8) {
        int j = j0 + tid;
        float ci0 = ec[i * 3], ci1 = ec[i * 3 + 1], ci2 = ec[i * 3 + 2];
        float cj0 = ec[j * 3], cj1 = ec[j * 3 + 1], cj2 = ec[j * 3 + 2];
        float dx = ci0 - cj0, dy = ci1 - cj1, dz = ci2 - cj2;
        float dist = sqrtf(dx * dx + dy * dy + dz * dz) + 1e-8f;
        dist = fminf(fmaxf(dist, 1e-8f), 1e8f);
        float dot = ci0 * cj0 + ci1 * cj1 + ci2 * cj2;
        dot = fminf(fmaxf(dot, -1e8f), 1e8f);
        s_dist[tid] = dist;
        s_dot[tid] = dot;
    }
    __syncthreads();

    for (int t2 = tid; t2 < 512; t2 += 256) {
        int p = t2 >> 6, r = t2 & 63;
        float d = s_dist[p];
        float dd = d - rc[r];
        s_rbf[t2] = (d <= 10.0f) ? __expf(-rw[r] * dd * dd) : 0.0f;
    }
    __syncthreads();

    // layer-1: base (geometric, head-indep) + qc + kc -> silu -> s_x1
    {
        int c = tid & 127, half = tid >> 7;
        for (int pp = half; pp < 8; pp += 2) {
            float acc = ab1[c];
            const float* rb = s_rbf + pp * 64;
#pragma unroll 8
            for (int r = 0; r < 64; r++) acc += rb[r] * s_w1r[r * HIDN + c];
            acc += s_dot[pp] * s_w1r[64 * HIDN + c];
            int j = j0 + pp;
#pragma unroll
            for (int h = 0; h < NHD; h++) {
                float xv = acc + s_qc[h * HIDN + c] + g_kc[(j * NHD + h) * HIDN + c];
                s_x1[h * 1024 + c * 8 + pp] = silu_f(xv);
            }
        }
    }
    __syncthreads();

    // layer-2 (128x128 matvec, 8 pairs register-blocked, f32x2) + layer-3 column h
    {
        int h = warp;
        int c0 = lane * 4;
        ull acc[4][4];
#pragma unroll
        for (int a = 0; a < 4; a++)
#pragma unroll
            for (int b = 0; b < 4; b++) acc[a][b] = 0ULL;

        const float4 b2v = *reinterpret_cast<const float4*>(&ab2[c0]);
        float b2a[4] = {b2v.x, b2v.y, b2v.z, b2v.w};
        float w3a[4];
#pragma unroll
        for (int col = 0; col < 4; col++) w3a[col] = aw3[(c0 + col) * NHD + h];

        const float* xb = s_x1 + h * 1024;
#pragma unroll 2
        for (int cin = 0; cin < 128; cin++) {
            float4 w = *reinterpret_cast<const float4*>(&s_w2[cin * HIDN + c0]);
            ull w0 = pack2(w.x, w.x);
            ull w1 = pack2(w.y, w.y);
            ull w2 = pack2(w.z, w.z);
            ull w3 = pack2(w.w, w.w);
            const ull* xx = reinterpret_cast<const ull*>(xb + cin * 8);
#pragma unroll
            for (int p2 = 0; p2 < 4; p2++) {
                ull xv = xx[p2];
                fma2(acc[p2][0], xv, w0);
                fma2(acc[p2][1], xv, w1);
                fma2(acc[p2][2], xv, w2);
                fma2(acc[p2][3], xv, w3);
            }
        }

#pragma unroll
        for (int p2 = 0; p2 < 4; p2++) {
            float lo[4], hi[4];
#pragma unroll
            for (int col = 0; col < 4; col++) unpack2(acc[p2][col], lo[col], hi[col]);
#pragma unroll
            for (int par = 0; par < 2; par++) {
                float part = 0.f;
#pragma unroll
                for (int col = 0; col < 4; col++) {
                    float v = par ? hi[col] : lo[col];
                    float x2 = silu_f(v + b2a[col]);
                    part += x2 * w3a[col];
                }
                part = wsum(part);
                if (lane == 0) {
                    int j = j0 + p2 * 2 + par;
                    float s = part + ab3[h] + mask[i * N_E + j];
                    s = fminf(fmaxf(s, -1e9f), 1e9f);
                    g_scores[(h * N_E + i) * N_E + j] = s;
                }
            }
        }
    }
}

// ---------------- kernel 5: softmax + feats + coord update ----------------
__global__ void k_soft(const float* __restrict__ ec, float* __restrict__ out) {
    int i = blockIdx.x, tid = threadIdx.x, lane = tid & 31, wid = tid >> 5;
    int j = tid;  // 384 threads
    __shared__ float s_r[12];
    __shared__ float s_feat[12 * 16];
    __shared__ float s_b;

    float ci0 = ec[i * 3], ci1 = ec[i * 3 + 1], ci2 = ec[i * 3 + 2];
    float cj0 = ec[j * 3], cj1 = ec[j * 3 + 1], cj2 = ec[j * 3 + 2];
    float ca0 = 0.f, ca1 = 0.f, ca2 = 0.f;

    for (int h = 0; h < NHD; h++) {
        float sc = g_scores[(h * N_E + i) * N_E + j];
        float m = wmax(sc);
        if (lane == 0) s_r[wid] = m;
        __syncthreads();
        if (tid == 0) {
            float mm = s_r[0];
            for (int w = 1; w < 12; w++) mm = fmaxf(mm, s_r[w]);
            s_b = mm;
        }
        __syncthreads();
        float e = __expf(sc - s_b);
        float su = wsum(e);
        if (lane == 0) s_r[wid] = su;
        __syncthreads();
        if (tid == 0) {
            float ss = 0.f;
            for (int w = 0; w < 12; w++) ss += s_r[w];
            s_b = ss;
        }
        __syncthreads();
        float attn = __fdividef(e, s_b);

        // feats[h] = attn @ v[:,h,:]
        float part[16];
        const float* vrow = g_v + j * HIDN + h * DHD;
#pragma unroll
        for (int d = 0; d < 16; d++) part[d] = attn * vrow[d];
#pragma unroll
        for (int d = 0; d < 16; d++) part[d] = wsum(part[d]);
        if (lane == 0) {
#pragma unroll
            for (int d = 0; d < 16; d++) s_feat[wid * 16 + d] = part[d];
        }
        __syncthreads();
        if (tid < 16) {
            float a = 0.f;
            for (int w = 0; w < 12; w++) a += s_feat[w * 16 + tid];
            g_upd[i * HIDN + h * DHD + tid] = a;
        }
        // coords: gate indexed by query row i
        float ga = g_gate[i * NHD + h] * attn;
        ca0 += ga * (ci0 - cj0);
        ca1 += ga * (ci1 - cj1);
        ca2 += ga * (ci2 - cj2);
        __syncthreads();
    }

    float cv[3] = {ca0, ca1, ca2};
    for (int d = 0; d < 3; d++) {
        float v = wsum(cv[d]);
        if (lane == 0) s_r[wid] = v;
        __syncthreads();
        if (tid == 0) {
            float t = 0.f;
            for (int w = 0; w < 12; w++) t += s_r[w];
            out[N_E * HIDN + i * 3 + d] = ec[i * 3 + d] + t * 0.125f;
        }
        __syncthreads();
    }
}

// ---------------- kernel 6: output projection + layernorm ----------------
__global__ void k_out(const float* __restrict__ ef, const float* __restrict__ wo,
                      const float* __restrict__ bo, const float* __restrict__ lng,
                      const float* __restrict__ lnb, float* __restrict__ out) {
    int i = blockIdx.x, t = threadIdx.x, lane = t & 31, wid = t >> 5;
    __shared__ float s_u[HIDN];
    __shared__ float s_r[4];
    __shared__ float s_b;
    s_u[t] = g_upd[i * HIDN + t];
    __syncthreads();
    float acc = ef[i * HIDN + t] + bo[t];
#pragma unroll 4
    for (int c = 0; c < HIDN; c++) acc += s_u[c] * wo[c * HIDN + t];
    float m = wsum(acc);
    if (lane == 0) s_r[wid] = m;
    __syncthreads();
    if (t == 0) s_b = (s_r[0] + s_r[1] + s_r[2] + s_r[3]) * (1.0f / 128.0f);
    __syncthreads();
    float mu = s_b;
    float d = acc - mu;
    float v = wsum(d * d);
    __syncthreads();
    if (lane == 0) s_r[wid] = v;
    __syncthreads();
    if (t == 0) s_b = (s_r[0] + s_r[1] + s_r[2] + s_r[3]) * (1.0f / 128.0f);
    __syncthreads();
    out[i * HIDN + t] = d * rsqrtf(s_b + 1e-5f) * lng[t] + lnb[t];
}

// ---------------- launch ----------------
extern "C" void kernel_launch(void* const* d_in, const int* in_sizes, int n_in,
                              void* d_out, int out_size) {
    const float* ef = (const float*)d_in[0];
    const float* ec = (const float*)d_in[1];
    const float* mask = (const float*)d_in[2];
    const float* wq = (const float*)d_in[3];
    const float* wk = (const float*)d_in[4];
    const float* wv = (const float*)d_in[5];
    const float* rc = (const float*)d_in[6];
    const float* rw = (const float*)d_in[7];
    const float* aw1 = (const float*)d_in[8];
    const float* ab1 = (const float*)d_in[9];
    const float* aw2 = (const float*)d_in[10];
    const float* ab2 = (const float*)d_in[11];
    const float* aw3 = (const float*)d_in[12];
    const float* ab3 = (const float*)d_in[13];
    const float* gw1 = (const float*)d_in[14];
    const float* gb1 = (const float*)d_in[15];
    const float* gw2 = (const float*)d_in[16];
    const float* gb2 = (const float*)d_in[17];
    const float* wo = (const float*)d_in[18];
    const float* bo = (const float*)d_in[19];
    const float* lng = (const float*)d_in[20];
    const float* lnb = (const float*)d_in[21];
    float* out = (float*)d_out;

    k_qkv<<<N_E, 128>>>(ef, wq, wk, wv);
    k_qckc<<<dim3(N_E, NHD), 128>>>(aw1);
    k_gate<<<dim3(N_E, NHD), 128>>>(gw1, gb1, gw2, gb2);

    cudaFuncSetAttribute(k_pair, cudaFuncAttributeMaxDynamicSharedMemorySize, K4_SMEM_BYTES);
    k_pair<<<dim3(N_E, 48), 256, K4_SMEM_BYTES>>>(ec, rc, rw, aw1, ab1, aw2, ab2, aw3, ab3, mask);

    k_soft<<<N_E, N_E>>>(ec, out);
    k_out<<<N_E, 128>>>(ef, wo, bo, lng, lnb, out);
}

// round 2
// speedup vs baseline: 1.3158x; 1.3158x over previous
#include <cuda_runtime.h>

#define N_E 384
#define HIDN 128
#define NHD 8
#define DHD 16
#define NRB 64
#define PAIRS 16
#define NJB (N_E / PAIRS)

typedef unsigned long long ull;

// ---------------- scratch ----------------
__device__ float g_q[N_E * HIDN];
__device__ float g_k[N_E * HIDN];
__device__ float g_v[N_E * HIDN];
__device__ float g_qc[N_E * NHD * HIDN];
__device__ float g_kc[N_E * NHD * HIDN];
__device__ float g_gate[N_E * NHD];
__device__ float g_scores[NHD * N_E * N_E];
__device__ float g_upd[N_E * HIDN];
__device__ float g_cpart[N_E * NHD * 3];

// ---------------- helpers ----------------
__device__ __forceinline__ float silu_f(float x) {
    return __fdividef(x, 1.0f + __expf(-x));
}
__device__ __forceinline__ float wsum(float v) {
#pragma unroll
    for (int o = 16; o; o >>= 1) v += __shfl_xor_sync(0xffffffffu, v, o);
    return v;
}
__device__ __forceinline__ float wmax(float v) {
#pragma unroll
    for (int o = 16; o; o >>= 1) v = fmaxf(v, __shfl_xor_sync(0xffffffffu, v, o));
    return v;
}
__device__ __forceinline__ ull pack2(float lo, float hi) {
    ull r;
    asm("mov.b64 %0, {%1, %2};" : "=l"(r) : "f"(lo), "f"(hi));
    return r;
}
__device__ __forceinline__ void unpack2(ull v, float& lo, float& hi) {
    asm("mov.b64 {%0, %1}, %2;" : "=f"(lo), "=f"(hi) : "l"(v));
}
__device__ __forceinline__ void fma2(ull& d, ull a, ull b) {
    asm("fma.rn.f32x2 %0, %1, %2, %0;" : "+l"(d) : "l"(a), "l"(b));
}

// ---------------- kernel 1: q,k,v projections ----------------
__global__ void k_qkv(const float* __restrict__ ef, const float* __restrict__ wq,
                      const float* __restrict__ wk, const float* __restrict__ wv) {
    int i = blockIdx.x, t = threadIdx.x;
    __shared__ float s_e[HIDN];
    s_e[t] = ef[i * HIDN + t];
    __syncthreads();
    float aq = 0.f, ak = 0.f, av = 0.f;
#pragma unroll 4
    for (int c = 0; c < HIDN; c++) {
        float e = s_e[c];
        aq += e * wq[c * HIDN + t];
        ak += e * wk[c * HIDN + t];
        av += e * wv[c * HIDN + t];
    }
    g_q[i * HIDN + t] = aq;
    g_k[i * HIDN + t] = ak;
    g_v[i * HIDN + t] = av;
}

// ---------------- kernel 2: qc = q@a_w1[0:16], kc = k@a_w1[16:32] ----------------
__global__ void k_qckc(const float* __restrict__ aw1) {
    int i = blockIdx.x, h = blockIdx.y, t = threadIdx.x;
    const float* qr = g_q + i * HIDN + h * DHD;
    const float* kr = g_k + i * HIDN + h * DHD;
    float aq = 0.f, ak = 0.f;
#pragma unroll
    for (int d = 0; d < DHD; d++) {
        aq += qr[d] * aw1[d * HIDN + t];
        ak += kr[d] * aw1[(DHD + d) * HIDN + t];
    }
    g_qc[(i * NHD + h) * HIDN + t] = aq;
    g_kc[(i * NHD + h) * HIDN + t] = ak;
}

// ---------------- kernel 3: gates ----------------
__global__ void k_gate(const float* __restrict__ gw1, const float* __restrict__ gb1,
                       const float* __restrict__ gw2, const float* __restrict__ gb2) {
    int i = blockIdx.x, h = blockIdx.y, t = threadIdx.x;
    int lane = t & 31, wid = t >> 5;
    const float* vr = g_v + i * HIDN + h * DHD;
    float acc = gb1[t];
#pragma unroll
    for (int d = 0; d < DHD; d++) acc += vr[d] * gw1[d * HIDN + t];
    float p = silu_f(acc) * gw2[t];
    p = wsum(p);
    __shared__ float sr[4];
    if (lane == 0) sr[wid] = p;
    __syncthreads();
    if (t == 0) {
        float s = sr[0] + sr[1] + sr[2] + sr[3] + gb2[0];
        g_gate[i * NHD + h] = __fdividef(1.0f, 1.0f + __expf(-s));
    }
}

// ---------------- kernel 4: per-pair MLP -> scores ----------------
// smem floats: w2[16384] | w1r[8320] | x1[16384] | qc[1024] | rbf[1024] | dot[16] | dist[16]
#define K4_SMEM_FLOATS (16384 + 8320 + 16384 + 1024 + 1024 + 16 + 16)
#define K4_SMEM_BYTES (K4_SMEM_FLOATS * 4)

__global__ void __launch_bounds__(256, 1)
k_pair(const float* __restrict__ ec, const float* __restrict__ rc,
       const float* __restrict__ rw, const float* __restrict__ aw1,
       const float* __restrict__ ab1, const float* __restrict__ aw2,
       const float* __restrict__ ab2, const float* __restrict__ aw3,
       const float* __restrict__ ab3, const float* __restrict__ mask) {
    extern __shared__ float sm[];
    float* s_w2 = sm;               // [cin*128 + cout]
    float* s_w1r = s_w2 + 16384;    // a_w1 rows 32..96
    float* s_x1 = s_w1r + 8320;     // [h][p2][cin][par] : h*2048 + p2*256 + cin*2 + par
    float* s_qc = s_x1 + 16384;     // [h][c]
    float* s_rbf = s_qc + 1024;     // [p][r]
    float* s_dot = s_rbf + 1024;
    float* s_dist = s_dot + 16;

    int i = blockIdx.x;
    int j0 = blockIdx.y * PAIRS;
    int tid = threadIdx.x, lane = tid & 31, warp = tid >> 5;

    for (int idx = tid; idx < 16384; idx += 256) s_w2[idx] = aw2[idx];
    for (int idx = tid; idx < 8320; idx += 256) s_w1r[idx] = aw1[32 * HIDN + idx];
    for (int idx = tid; idx < 1024; idx += 256) s_qc[idx] = g_qc[i * 1024 + idx];

    // stage kc rows for the 16 j's into x1 buffer (in-place consumed by layer-1)
    for (int idx = tid; idx < 16384; idx += 256) {
        int jj = idx >> 10;           // 0..15
        int rem = idx & 1023;
        int h = rem >> 7, c = rem & 127;
        int dst = h * 2048 + (jj >> 1) * 256 + c * 2 + (jj & 1);
        s_x1[dst] = g_kc[(j0 + jj) * 1024 + rem];
    }

    if (tid < PAIRS) {
        int j = j0 + tid;
        float ci0 = ec[i * 3], ci1 = ec[i * 3 + 1], ci2 = ec[i * 3 + 2];
        float cj0 = ec[j * 3], cj1 = ec[j * 3 + 1], cj2 = ec[j * 3 + 2];
        float dx = ci0 - cj0, dy = ci1 - cj1, dz = ci2 - cj2;
        float dist = sqrtf(dx * dx + dy * dy + dz * dz) + 1e-8f;
        dist = fminf(fmaxf(dist, 1e-8f), 1e8f);
        float dot = ci0 * cj0 + ci1 * cj1 + ci2 * cj2;
        dot = fminf(fmaxf(dot, -1e8f), 1e8f);
        s_dist[tid] = dist;
        s_dot[tid] = dot;
    }
    __syncthreads();

    for (int t2 = tid; t2 < PAIRS * 64; t2 += 256) {
        int p = t2 >> 6, r = t2 & 63;
        float d = s_dist[p];
        float dd = d - rc[r];
        s_rbf[t2] = (d <= 10.0f) ? __expf(-rw[r] * dd * dd) : 0.0f;
    }
    __syncthreads();

    // layer-1: geometric base (2 pairs at a time) + qc + kc -> silu -> x1 (in place)
    {
        int c = tid & 127, half = tid >> 7;
        float bias = ab1[c];
        for (int p2 = half; p2 < 8; p2 += 2) {
            int pp0 = 2 * p2, pp1 = pp0 + 1;
            float acc0 = bias, acc1 = bias;
            const float* rb0 = s_rbf + pp0 * 64;
            const float* rb1 = s_rbf + pp1 * 64;
#pragma unroll 8
            for (int r = 0; r < 64; r++) {
                float w = s_w1r[r * HIDN + c];
                acc0 += rb0[r] * w;
                acc1 += rb1[r] * w;
            }
            {
                float w = s_w1r[64 * HIDN + c];
                acc0 += s_dot[pp0] * w;
                acc1 += s_dot[pp1] * w;
            }
#pragma unroll
            for (int h = 0; h < NHD; h++) {
                int a = h * 2048 + p2 * 256 + c * 2;
                float qcv = s_qc[h * HIDN + c];
                float x0 = silu_f(acc0 + qcv + s_x1[a]);
                float x1v = silu_f(acc1 + qcv + s_x1[a + 1]);
                *reinterpret_cast<ull*>(&s_x1[a]) = pack2(x0, x1v);
            }
        }
    }
    __syncthreads();

    // layer-2: 128x128 matvec, 16 pairs register-blocked, f32x2; then layer-3 column h
    {
        int h = warp;
        int c0 = lane * 4;
        ull acc[8][4];
#pragma unroll
        for (int a = 0; a < 8; a++)
#pragma unroll
            for (int b = 0; b < 4; b++) acc[a][b] = 0ULL;

        const float4 b2v = *reinterpret_cast<const float4*>(&ab2[c0]);
        float b2a[4] = {b2v.x, b2v.y, b2v.z, b2v.w};
        float w3a[4];
#pragma unroll
        for (int col = 0; col < 4; col++) w3a[col] = aw3[(c0 + col) * NHD + h];

        const float* xb = s_x1 + h * 2048;
#pragma unroll 2
        for (int cin = 0; cin < 128; cin += 2) {
            float4 wA = *reinterpret_cast<const float4*>(&s_w2[cin * HIDN + c0]);
            float4 wB = *reinterpret_cast<const float4*>(&s_w2[(cin + 1) * HIDN + c0]);
            ull wa0 = pack2(wA.x, wA.x), wa1 = pack2(wA.y, wA.y);
            ull wa2 = pack2(wA.z, wA.z), wa3 = pack2(wA.w, wA.w);
            ull wb0 = pack2(wB.x, wB.x), wb1 = pack2(wB.y, wB.y);
            ull wb2 = pack2(wB.z, wB.z), wb3 = pack2(wB.w, wB.w);
#pragma unroll
            for (int p2 = 0; p2 < 8; p2++) {
                longlong2 xv = *reinterpret_cast<const longlong2*>(xb + p2 * 256 + cin * 2);
                ull x0 = (ull)xv.x, x1 = (ull)xv.y;
                fma2(acc[p2][0], x0, wa0);
                fma2(acc[p2][1], x0, wa1);
                fma2(acc[p2][2], x0, wa2);
                fma2(acc[p2][3], x0, wa3);
                fma2(acc[p2][0], x1, wb0);
                fma2(acc[p2][1], x1, wb1);
                fma2(acc[p2][2], x1, wb2);
                fma2(acc[p2][3], x1, wb3);
            }
        }

#pragma unroll
        for (int p2 = 0; p2 < 8; p2++) {
            float lo[4], hi[4];
#pragma unroll
            for (int col = 0; col < 4; col++) unpack2(acc[p2][col], lo[col], hi[col]);
#pragma unroll
            for (int par = 0; par < 2; par++) {
                float part = 0.f;
#pragma unroll
                for (int col = 0; col < 4; col++) {
                    float v = par ? hi[col] : lo[col];
                    part += silu_f(v + b2a[col]) * w3a[col];
                }
                part = wsum(part);
                if (lane == 0) {
                    int j = j0 + p2 * 2 + par;
                    float s = part + ab3[h] + mask[i * N_E + j];
                    s = fminf(fmaxf(s, -1e9f), 1e9f);
                    g_scores[(h * N_E + i) * N_E + j] = s;
                }
            }
        }
    }
}

// ---------------- kernel 5: softmax + feats + coord partials (per i,h) ----------------
__global__ void k_soft(const float* __restrict__ ec) {
    int i = blockIdx.x, h = blockIdx.y;
    int tid = threadIdx.x, lane = tid & 31, wid = tid >> 5;
    int j = tid;  // 384 threads
    __shared__ float s_r[12];
    __shared__ float s_feat[12 * 16];
    __shared__ float s_c[12 * 3];
    __shared__ float s_b;

    float sc = g_scores[(h * N_E + i) * N_E + j];
    float m = wmax(sc);
    if (lane == 0) s_r[wid] = m;
    __syncthreads();
    if (tid == 0) {
        float mm = s_r[0];
        for (int w = 1; w < 12; w++) mm = fmaxf(mm, s_r[w]);
        s_b = mm;
    }
    __syncthreads();
    float e = __expf(sc - s_b);
    float su = wsum(e);
    if (lane == 0) s_r[wid] = su;
    __syncthreads();
    if (tid == 0) {
        float ss = 0.f;
        for (int w = 0; w < 12; w++) ss += s_r[w];
        s_b = ss;
    }
    __syncthreads();
    float attn = __fdividef(e, s_b);

    // feats
    float part[16];
    const float* vrow = g_v + j * HIDN + h * DHD;
#pragma unroll
    for (int d = 0; d < 16; d++) part[d] = attn * vrow[d];
#pragma unroll
    for (int d = 0; d < 16; d++) part[d] = wsum(part[d]);
    if (lane == 0) {
#pragma unroll
        for (int d = 0; d < 16; d++) s_feat[wid * 16 + d] = part[d];
    }

    // coord partial
    float ga = g_gate[i * NHD + h] * attn;
    float cv[3];
    cv[0] = ga * (ec[i * 3 + 0] - ec[j * 3 + 0]);
    cv[1] = ga * (ec[i * 3 + 1] - ec[j * 3 + 1]);
    cv[2] = ga * (ec[i * 3 + 2] - ec[j * 3 + 2]);
#pragma unroll
    for (int d = 0; d < 3; d++) {
        float v = wsum(cv[d]);
        if (lane == 0) s_c[wid * 3 + d] = v;
    }
    __syncthreads();
    if (tid < 16) {
        float a = 0.f;
        for (int w = 0; w < 12; w++) a += s_feat[w * 16 + tid];
        g_upd[i * HIDN + h * DHD + tid] = a;
    }
    if (tid >= 32 && tid < 35) {
        int d = tid - 32;
        float a = 0.f;
        for (int w = 0; w < 12; w++) a += s_c[w * 3 + d];
        g_cpart[(i * NHD + h) * 3 + d] = a;
    }
}

// ---------------- kernel 6: output projection + layernorm + coord finalize ----------------
__global__ void k_out(const float* __restrict__ ef, const float* __restrict__ wo,
                      const float* __restrict__ bo, const float* __restrict__ lng,
                      const float* __restrict__ lnb, const float* __restrict__ ec,
                      float* __restrict__ out) {
    int i = blockIdx.x, t = threadIdx.x, lane = t & 31, wid = t >> 5;
    __shared__ float s_u[HIDN];
    __shared__ float s_r[4];
    __shared__ float s_b;
    s_u[t] = g_upd[i * HIDN + t];
    __syncthreads();
    float acc = ef[i * HIDN + t] + bo[t];
#pragma unroll 4
    for (int c = 0; c < HIDN; c++) acc += s_u[c] * wo[c * HIDN + t];
    float m = wsum(acc);
    if (lane == 0) s_r[wid] = m;
    __syncthreads();
    if (t == 0) s_b = (s_r[0] + s_r[1] + s_r[2] + s_r[3]) * (1.0f / 128.0f);
    __syncthreads();
    float mu = s_b;
    float d = acc - mu;
    float v = wsum(d * d);
    __syncthreads();
    if (lane == 0) s_r[wid] = v;
    __syncthreads();
    if (t == 0) s_b = (s_r[0] + s_r[1] + s_r[2] + s_r[3]) * (1.0f / 128.0f);
    __syncthreads();
    out[i * HIDN + t] = d * rsqrtf(s_b + 1e-5f) * lng[t] + lnb[t];
    if (t < 3) {
        float a = 0.f;
#pragma unroll
        for (int h = 0; h < NHD; h++) a += g_cpart[(i * NHD + h) * 3 + t];
        out[N_E * HIDN + i * 3 + t] = ec[i * 3 + t] + a * 0.125f;
    }
}

// ---------------- launch ----------------
extern "C" void kernel_launch(void* const* d_in, const int* in_sizes, int n_in,
                              void* d_out, int out_size) {
    const float* ef = (const float*)d_in[0];
    const float* ec = (const float*)d_in[1];
    const float* mask = (const float*)d_in[2];
    const float* wq = (const float*)d_in[3];
    const float* wk = (const float*)d_in[4];
    const float* wv = (const float*)d_in[5];
    const float* rc = (const float*)d_in[6];
    const float* rw = (const float*)d_in[7];
    const float* aw1 = (const float*)d_in[8];
    const float* ab1 = (const float*)d_in[9];
    const float* aw2 = (const float*)d_in[10];
    const float* ab2 = (const float*)d_in[11];
    const float* aw3 = (const float*)d_in[12];
    const float* ab3 = (const float*)d_in[13];
    const float* gw1 = (const float*)d_in[14];
    const float* gb1 = (const float*)d_in[15];
    const float* gw2 = (const float*)d_in[16];
    const float* gb2 = (const float*)d_in[17];
    const float* wo = (const float*)d_in[18];
    const float* bo = (const float*)d_in[19];
    const float* lng = (const float*)d_in[20];
    const float* lnb = (const float*)d_in[21];
    float* out = (float*)d_out;

    k_qkv<<<N_E, 128>>>(ef, wq, wk, wv);
    k_qckc<<<dim3(N_E, NHD), 128>>>(aw1);
    k_gate<<<dim3(N_E, NHD), 128>>>(gw1, gb1, gw2, gb2);

    cudaFuncSetAttribute(k_pair, cudaFuncAttributeMaxDynamicSharedMemorySize, K4_SMEM_BYTES);
    k_pair<<<dim3(N_E, NJB), 256, K4_SMEM_BYTES>>>(ec, rc, rw, aw1, ab1, aw2, ab2, aw3, ab3, mask);

    k_soft<<<dim3(N_E, NHD), N_E>>>(ec);
    k_out<<<N_E, 128>>>(ef, wo, bo, lng, lnb, ec, out);
}

// round 5
// speedup vs baseline: 2.3016x; 1.7492x over previous
#include <cuda_runtime.h>
#include <cuda_bf16.h>
#include <cstdint>

#define N_E 384
#define HIDN 128
#define NHD 8
#define DHD 16
#define PAIRS 16
#define NJB (N_E / PAIRS)     // 24
#define NTILES (N_E * NJB)    // 9216
#define NBLK 148

typedef unsigned long long ull;

// ---------------- scratch ----------------
__device__ float g_q[N_E * HIDN];
__device__ float g_k[N_E * HIDN];
__device__ float g_v[N_E * HIDN];
__device__ float g_qc[N_E * NHD * HIDN];
__device__ float g_kc[N_E * NHD * HIDN];
__device__ float g_gate[N_E * NHD];
__device__ float g_scores[NHD * N_E * N_E];
__device__ float g_upd[N_E * HIDN];
__device__ float g_cpart[N_E * NHD * 3];
__device__ __nv_bfloat16 g_w2t_hi[HIDN * HIDN];  // [cout][cin]
__device__ __nv_bfloat16 g_w2t_lo[HIDN * HIDN];

// ---------------- helpers ----------------
__device__ __forceinline__ float silu_f(float x) {
    return __fdividef(x, 1.0f + __expf(-x));
}
__device__ __forceinline__ float wsum(float v) {
#pragma unroll
    for (int o = 16; o; o >>= 1) v += __shfl_xor_sync(0xffffffffu, v, o);
    return v;
}
__device__ __forceinline__ float wmax(float v) {
#pragma unroll
    for (int o = 16; o; o >>= 1) v = fmaxf(v, __shfl_xor_sync(0xffffffffu, v, o));
    return v;
}
// bf16 m16n8k16 HMMA, D += A*B
__device__ __forceinline__ void mma16816(float* c, const uint32_t* a, const uint32_t* b) {
    asm volatile(
        "mma.sync.aligned.m16n8k16.row.col.f32.bf16.bf16.f32 "
        "{%0,%1,%2,%3}, {%4,%5,%6,%7}, {%8,%9}, {%0,%1,%2,%3};"
        : "+f"(c[0]), "+f"(c[1]), "+f"(c[2]), "+f"(c[3])
        : "r"(a[0]), "r"(a[1]), "r"(a[2]), "r"(a[3]), "r"(b[0]), "r"(b[1]));
}
// swizzled byte offset into a [128 rows x 256B] bf16 tile: XOR 16B-unit by (m&7)
__device__ __forceinline__ uint32_t swz(int m, int cbyte) {
    return (uint32_t)(m * 256 + (cbyte ^ ((m & 7) << 4)));
}

// ---------------- kernel 1: q,k,v projections ----------------
__global__ void k_qkv(const float* __restrict__ ef, const float* __restrict__ wq,
                      const float* __restrict__ wk, const float* __restrict__ wv) {
    int i = blockIdx.x, t = threadIdx.x;
    __shared__ float s_e[HIDN];
    s_e[t] = ef[i * HIDN + t];
    __syncthreads();
    float aq = 0.f, ak = 0.f, av = 0.f;
#pragma unroll 4
    for (int c = 0; c < HIDN; c++) {
        float e = s_e[c];
        aq += e * wq[c * HIDN + t];
        ak += e * wk[c * HIDN + t];
        av += e * wv[c * HIDN + t];
    }
    g_q[i * HIDN + t] = aq;
    g_k[i * HIDN + t] = ak;
    g_v[i * HIDN + t] = av;
}

// ---------------- kernel 2: qc/kc ----------------
__global__ void k_qckc(const float* __restrict__ aw1) {
    int i = blockIdx.x, h = blockIdx.y, t = threadIdx.x;
    const float* qr = g_q + i * HIDN + h * DHD;
    const float* kr = g_k + i * HIDN + h * DHD;
    float aq = 0.f, ak = 0.f;
#pragma unroll
    for (int d = 0; d < DHD; d++) {
        aq += qr[d] * aw1[d * HIDN + t];
        ak += kr[d] * aw1[(DHD + d) * HIDN + t];
    }
    g_qc[(i * NHD + h) * HIDN + t] = aq;
    g_kc[(i * NHD + h) * HIDN + t] = ak;
}

// ---------------- kernel 3: gates ----------------
__global__ void k_gate(const float* __restrict__ gw1, const float* __restrict__ gb1,
                       const float* __restrict__ gw2, const float* __restrict__ gb2) {
    int i = blockIdx.x, h = blockIdx.y, t = threadIdx.x;
    int lane = t & 31, wid = t >> 5;
    const float* vr = g_v + i * HIDN + h * DHD;
    float acc = gb1[t];
#pragma unroll
    for (int d = 0; d < DHD; d++) acc += vr[d] * gw1[d * HIDN + t];
    float p = silu_f(acc) * gw2[t];
    p = wsum(p);
    __shared__ float sr[4];
    if (lane == 0) sr[wid] = p;
    __syncthreads();
    if (t == 0) {
        float s = sr[0] + sr[1] + sr[2] + sr[3] + gb2[0];
        g_gate[i * NHD + h] = __fdividef(1.0f, 1.0f + __expf(-s));
    }
}

// ---------------- kernel 3b: split w2^T into bf16 hi/lo ----------------
__global__ void k_w2t(const float* __restrict__ aw2) {
    int idx = blockIdx.x * 256 + threadIdx.x;  // 16384
    int cout = idx >> 7, cin = idx & 127;
    float w = aw2[cin * HIDN + cout];
    __nv_bfloat16 hi = __float2bfloat16_rn(w);
    float lo = w - __bfloat162float(hi);
    g_w2t_hi[idx] = hi;
    g_w2t_lo[idx] = __float2bfloat16_rn(lo);
}

// ---------------- kernel 4: persistent pair-MLP with HMMA bf16 ----------------
// smem byte map
#define A_HI_OFF 0          // 32768  [128 m][256B] swizzled bf16
#define A_LO_OFF 32768      // 32768
#define W1R_OFF 65536       // 8320 f
#define QC_OFF 98816        // 1024 f
#define RBF_OFF 102912      // 1024 f
#define W3_OFF 107008       // 1024 f  [col*8+h]
#define B2_OFF 111104       // 128 f
#define AB3_OFF 111616      // 8 f
#define RC_OFF 111648       // 64 f
#define RW_OFF 111904       // 64 f
#define DOT_OFF 112160      // 16 f
#define DIST_OFF 112224     // 16 f
#define SPART_OFF 112288    // 128 f
#define K4_SMEM_BYTES 112800

__global__ void __launch_bounds__(256, 1)
k_pair(const float* __restrict__ ec, const float* __restrict__ rc,
       const float* __restrict__ rw, const float* __restrict__ aw1,
       const float* __restrict__ ab1, const float* __restrict__ ab2,
       const float* __restrict__ aw3, const float* __restrict__ ab3,
       const float* __restrict__ mask) {
    extern __shared__ char sm[];
    float* s_w1r = (float*)(sm + W1R_OFF);
    float* s_qc = (float*)(sm + QC_OFF);
    float* s_rbf = (float*)(sm + RBF_OFF);
    float* s_w3 = (float*)(sm + W3_OFF);
    float* s_b2 = (float*)(sm + B2_OFF);
    float* s_ab3 = (float*)(sm + AB3_OFF);
    float* s_rc = (float*)(sm + RC_OFF);
    float* s_rw = (float*)(sm + RW_OFF);
    float* s_dot = (float*)(sm + DOT_OFF);
    float* s_dist = (float*)(sm + DIST_OFF);
    float* s_part = (float*)(sm + SPART_OFF);

    int tid = threadIdx.x, lane = tid & 31, warp = tid >> 5;
    int gid = lane >> 2, tid4 = lane & 3;

    // ---- one-time init ----
    for (int idx = tid; idx < 8320; idx += 256) s_w1r[idx] = aw1[32 * HIDN + idx];
    for (int idx = tid; idx < 1024; idx += 256) s_w3[idx] = aw3[idx];
    if (tid < 128) s_b2[tid] = ab2[tid];
    if (tid < 8) s_ab3[tid] = ab3[tid];
    if (tid < 64) {
        s_rc[tid] = rc[tid];
        s_rw[tid] = rw[tid];
    }

    // B fragments (w2^T hi/lo) permanently in registers: warp owns couts [warp*16, warp*16+16)
    uint32_t Bh[2][8][2], Bl[2][8][2];
#pragma unroll
    for (int nb = 0; nb < 2; nb++)
#pragma unroll
        for (int kb = 0; kb < 8; kb++) {
            int n = warp * 16 + nb * 8 + gid;
            int k = kb * 16 + tid4 * 2;
            Bh[nb][kb][0] = *(const uint32_t*)(g_w2t_hi + n * HIDN + k);
            Bh[nb][kb][1] = *(const uint32_t*)(g_w2t_hi + n * HIDN + k + 8);
            Bl[nb][kb][0] = *(const uint32_t*)(g_w2t_lo + n * HIDN + k);
            Bl[nb][kb][1] = *(const uint32_t*)(g_w2t_lo + n * HIDN + k + 8);
        }
    __syncthreads();

    for (int tile = blockIdx.x; tile < NTILES; tile += NBLK) {
        int i = tile / NJB;
        int j0 = (tile % NJB) * PAIRS;

        // ---- setup: qc, dist/dot, zero s_part ----
        if (tid < 128) s_part[tid] = 0.f;
        {
            // 256 threads x float4 = 1024 floats
            *(float4*)(&s_qc[tid * 4]) = *(const float4*)(&g_qc[i * 1024 + tid * 4]);
        }
        if (tid < PAIRS) {
            int j = j0 + tid;
            float ci0 = ec[i * 3], ci1 = ec[i * 3 + 1], ci2 = ec[i * 3 + 2];
            float cj0 = ec[j * 3], cj1 = ec[j * 3 + 1], cj2 = ec[j * 3 + 2];
            float dx = ci0 - cj0, dy = ci1 - cj1, dz = ci2 - cj2;
            float dist = sqrtf(dx * dx + dy * dy + dz * dz) + 1e-8f;
            dist = fminf(fmaxf(dist, 1e-8f), 1e8f);
            float dot = ci0 * cj0 + ci1 * cj1 + ci2 * cj2;
            dot = fminf(fmaxf(dot, -1e8f), 1e8f);
            s_dist[tid] = dist;
            s_dot[tid] = dot;
        }
        __syncthreads();
        for (int t2 = tid; t2 < PAIRS * 64; t2 += 256) {
            int p = t2 >> 6, r = t2 & 63;
            float d = s_dist[p];
            float dd = d - s_rc[r];
            s_rbf[t2] = (d <= 10.0f) ? __expf(-s_rw[r] * dd * dd) : 0.0f;
        }
        __syncthreads();

        // ---- layer-1: x1 = silu(base + qc + kc) -> A_hi/A_lo bf16 (swizzled) ----
        {
            int c = tid & 127, half = tid >> 7;
            float bias = ab1[c];
            for (int p2 = half; p2 < 8; p2 += 2) {
                int pp0 = 2 * p2, pp1 = pp0 + 1;
                float acc0 = bias, acc1 = bias;
                const float* rb0 = s_rbf + pp0 * 64;
                const float* rb1 = s_rbf + pp1 * 64;
#pragma unroll 8
                for (int r = 0; r < 64; r++) {
                    float w = s_w1r[r * HIDN + c];
                    acc0 += rb0[r] * w;
                    acc1 += rb1[r] * w;
                }
                {
                    float w = s_w1r[64 * HIDN + c];
                    acc0 += s_dot[pp0] * w;
                    acc1 += s_dot[pp1] * w;
                }
#pragma unroll
                for (int h = 0; h < NHD; h++) {
                    float qcv = s_qc[h * HIDN + c];
                    float kc0 = g_kc[((j0 + pp0) * NHD + h) * HIDN + c];
                    float kc1 = g_kc[((j0 + pp1) * NHD + h) * HIDN + c];
                    float x0 = silu_f(acc0 + qcv + kc0);
                    float x1 = silu_f(acc1 + qcv + kc1);
                    int m0 = h * PAIRS + pp0, m1 = h * PAIRS + pp1;
                    uint32_t o0 = swz(m0, c * 2), o1 = swz(m1, c * 2);
                    __nv_bfloat16 h0 = __float2bfloat16_rn(x0);
                    __nv_bfloat16 h1 = __float2bfloat16_rn(x1);
                    *(__nv_bfloat16*)(sm + A_HI_OFF + o0) = h0;
                    *(__nv_bfloat16*)(sm + A_HI_OFF + o1) = h1;
                    *(__nv_bfloat16*)(sm + A_LO_OFF + o0) =
                        __float2bfloat16_rn(x0 - __bfloat162float(h0));
                    *(__nv_bfloat16*)(sm + A_LO_OFF + o1) =
                        __float2bfloat16_rn(x1 - __bfloat162float(h1));
                }
            }
        }
        __syncthreads();

        // ---- HMMA: D = Ahi*Bhi + Alo*Bhi + Ahi*Blo (each warp: all M, 16 couts) ----
        float acc[8][2][4];
#pragma unroll
        for (int mb = 0; mb < 8; mb++)
#pragma unroll
            for (int nb = 0; nb < 2; nb++)
#pragma unroll
                for (int q = 0; q < 4; q++) acc[mb][nb][q] = 0.f;

#pragma unroll
        for (int kb = 0; kb < 8; kb++) {
#pragma unroll
            for (int mb = 0; mb < 8; mb++) {
                int m0 = mb * 16 + gid;
                int cb = kb * 32 + tid4 * 4;
                uint32_t ahi[4], alo[4];
                ahi[0] = *(const uint32_t*)(sm + A_HI_OFF + swz(m0, cb));
                ahi[1] = *(const uint32_t*)(sm + A_HI_OFF + swz(m0 + 8, cb));
                ahi[2] = *(const uint32_t*)(sm + A_HI_OFF + swz(m0, cb + 16));
                ahi[3] = *(const uint32_t*)(sm + A_HI_OFF + swz(m0 + 8, cb + 16));
                alo[0] = *(const uint32_t*)(sm + A_LO_OFF + swz(m0, cb));
                alo[1] = *(const uint32_t*)(sm + A_LO_OFF + swz(m0 + 8, cb));
                alo[2] = *(const uint32_t*)(sm + A_LO_OFF + swz(m0, cb + 16));
                alo[3] = *(const uint32_t*)(sm + A_LO_OFF + swz(m0 + 8, cb + 16));
#pragma unroll
                for (int nb = 0; nb < 2; nb++) {
                    mma16816(acc[mb][nb], ahi, Bh[nb][kb]);
                    mma16816(acc[mb][nb], alo, Bh[nb][kb]);
                    mma16816(acc[mb][nb], ahi, Bl[nb][kb]);
                }
            }
        }

        // ---- epilogue: silu(D + b2) . w3[:,h], reduce into s_part[row] ----
#pragma unroll
        for (int mb = 0; mb < 8; mb++) {
            float p0 = 0.f, p1 = 0.f;
#pragma unroll
            for (int nb = 0; nb < 2; nb++) {
                int c0 = warp * 16 + nb * 8 + tid4 * 2;
                float w30 = s_w3[c0 * NHD + mb], w31 = s_w3[(c0 + 1) * NHD + mb];
                float b20 = s_b2[c0], b21 = s_b2[c0 + 1];
                p0 += silu_f(acc[mb][nb][0] + b20) * w30 + silu_f(acc[mb][nb][1] + b21) * w31;
                p1 += silu_f(acc[mb][nb][2] + b20) * w30 + silu_f(acc[mb][nb][3] + b21) * w31;
            }
            p0 += __shfl_xor_sync(0xffffffffu, p0, 1);
            p0 += __shfl_xor_sync(0xffffffffu, p0, 2);
            p1 += __shfl_xor_sync(0xffffffffu, p1, 1);
            p1 += __shfl_xor_sync(0xffffffffu, p1, 2);
            if (tid4 == 0) {
                atomicAdd(&s_part[mb * 16 + gid], p0);
                atomicAdd(&s_part[mb * 16 + gid + 8], p1);
            }
        }
        __syncthreads();

        if (tid < 128) {
            int h = tid >> 4, p = tid & 15;
            int j = j0 + p;
            float s = s_part[tid] + s_ab3[h] + mask[i * N_E + j];
            s = fminf(fmaxf(s, -1e9f), 1e9f);
            g_scores[(h * N_E + i) * N_E + j] = s;
        }
        __syncthreads();
    }
}

// ---------------- kernel 5: softmax + feats + coord partials ----------------
__global__ void k_soft(const float* __restrict__ ec) {
    int i = blockIdx.x, h = blockIdx.y;
    int tid = threadIdx.x, lane = tid & 31, wid = tid >> 5;
    int j = tid;
    __shared__ float s_r[12];
    __shared__ float s_feat[12 * 16];
    __shared__ float s_c[12 * 3];
    __shared__ float s_b;

    float sc = g_scores[(h * N_E + i) * N_E + j];
    float m = wmax(sc);
    if (lane == 0) s_r[wid] = m;
    __syncthreads();
    if (tid == 0) {
        float mm = s_r[0];
        for (int w = 1; w < 12; w++) mm = fmaxf(mm, s_r[w]);
        s_b = mm;
    }
    __syncthreads();
    float e = __expf(sc - s_b);
    float su = wsum(e);
    if (lane == 0) s_r[wid] = su;
    __syncthreads();
    if (tid == 0) {
        float ss = 0.f;
        for (int w = 0; w < 12; w++) ss += s_r[w];
        s_b = ss;
    }
    __syncthreads();
    float attn = __fdividef(e, s_b);

    float part[16];
    const float* vrow = g_v + j * HIDN + h * DHD;
#pragma unroll
    for (int d = 0; d < 16; d++) part[d] = attn * vrow[d];
#pragma unroll
    for (int d = 0; d < 16; d++) part[d] = wsum(part[d]);
    if (lane == 0) {
#pragma unroll
        for (int d = 0; d < 16; d++) s_feat[wid * 16 + d] = part[d];
    }

    float ga = g_gate[i * NHD + h] * attn;
    float cv[3];
    cv[0] = ga * (ec[i * 3 + 0] - ec[j * 3 + 0]);
    cv[1] = ga * (ec[i * 3 + 1] - ec[j * 3 + 1]);
    cv[2] = ga * (ec[i * 3 + 2] - ec[j * 3 + 2]);
#pragma unroll
    for (int d = 0; d < 3; d++) {
        float v = wsum(cv[d]);
        if (lane == 0) s_c[wid * 3 + d] = v;
    }
    __syncthreads();
    if (tid < 16) {
        float a = 0.f;
        for (int w = 0; w < 12; w++) a += s_feat[w * 16 + tid];
        g_upd[i * HIDN + h * DHD + tid] = a;
    }
    if (tid >= 32 && tid < 35) {
        int d = tid - 32;
        float a = 0.f;
        for (int w = 0; w < 12; w++) a += s_c[w * 3 + d];
        g_cpart[(i * NHD + h) * 3 + d] = a;
    }
}

// ---------------- kernel 6: output proj + layernorm + coords ----------------
__global__ void k_out(const float* __restrict__ ef, const float* __restrict__ wo,
                      const float* __restrict__ bo, const float* __restrict__ lng,
                      const float* __restrict__ lnb, const float* __restrict__ ec,
                      float* __restrict__ out) {
    int i = blockIdx.x, t = threadIdx.x, lane = t & 31, wid = t >> 5;
    __shared__ float s_u[HIDN];
    __shared__ float s_r[4];
    __shared__ float s_b;
    s_u[t] = g_upd[i * HIDN + t];
    __syncthreads();
    float acc = ef[i * HIDN + t] + bo[t];
#pragma unroll 4
    for (int c = 0; c < HIDN; c++) acc += s_u[c] * wo[c * HIDN + t];
    float m = wsum(acc);
    if (lane == 0) s_r[wid] = m;
    __syncthreads();
    if (t == 0) s_b = (s_r[0] + s_r[1] + s_r[2] + s_r[3]) * (1.0f / 128.0f);
    __syncthreads();
    float mu = s_b;
    float d = acc - mu;
    float v = wsum(d * d);
    __syncthreads();
    if (lane == 0) s_r[wid] = v;
    __syncthreads();
    if (t == 0) s_b = (s_r[0] + s_r[1] + s_r[2] + s_r[3]) * (1.0f / 128.0f);
    __syncthreads();
    out[i * HIDN + t] = d * rsqrtf(s_b + 1e-5f) * lng[t] + lnb[t];
    if (t < 3) {
        float a = 0.f;
#pragma unroll
        for (int h = 0; h < NHD; h++) a += g_cpart[(i * NHD + h) * 3 + t];
        out[N_E * HIDN + i * 3 + t] = ec[i * 3 + t] + a * 0.125f;
    }
}

// ---------------- launch ----------------
extern "C" void kernel_launch(void* const* d_in, const int* in_sizes, int n_in,
                              void* d_out, int out_size) {
    const float* ef = (const float*)d_in[0];
    const float* ec = (const float*)d_in[1];
    const float* mask = (const float*)d_in[2];
    const float* wq = (const float*)d_in[3];
    const float* wk = (const float*)d_in[4];
    const float* wv = (const float*)d_in[5];
    const float* rc = (const float*)d_in[6];
    const float* rw = (const float*)d_in[7];
    const float* aw1 = (const float*)d_in[8];
    const float* ab1 = (const float*)d_in[9];
    const float* aw2 = (const float*)d_in[10];
    const float* ab2 = (const float*)d_in[11];
    const float* aw3 = (const float*)d_in[12];
    const float* ab3 = (const float*)d_in[13];
    const float* gw1 = (const float*)d_in[14];
    const float* gb1 = (const float*)d_in[15];
    const float* gw2 = (const float*)d_in[16];
    const float* gb2 = (const float*)d_in[17];
    const float* wo = (const float*)d_in[18];
    const float* bo = (const float*)d_in[19];
    const float* lng = (const float*)d_in[20];
    const float* lnb = (const float*)d_in[21];
    float* out = (float*)d_out;

    k_qkv<<<N_E, 128>>>(ef, wq, wk, wv);
    k_qckc<<<dim3(N_E, NHD), 128>>>(aw1);
    k_gate<<<dim3(N_E, NHD), 128>>>(gw1, gb1, gw2, gb2);
    k_w2t<<<64, 256>>>(aw2);

    cudaFuncSetAttribute(k_pair, cudaFuncAttributeMaxDynamicSharedMemorySize, K4_SMEM_BYTES);
    k_pair<<<NBLK, 256, K4_SMEM_BYTES>>>(ec, rc, rw, aw1, ab1, ab2, aw3, ab3, mask);

    k_soft<<<dim3(N_E, NHD), N_E>>>(ec);
    k_out<<<N_E, 128>>>(ef, wo, bo, lng, lnb, ec, out);
}

// round 6
// speedup vs baseline: 2.7895x; 1.2120x over previous
#include <cuda_runtime.h>
#include <cuda_bf16.h>
#include <cstdint>

#define N_E 384
#define HIDN 128
#define NHD 8
#define DHD 16
#define PAIRS 16
#define NJB (N_E / PAIRS)     // 24
#define NTILES (N_E * NJB)    // 9216
#define NBLK 148

typedef unsigned long long ull;

// ---------------- scratch ----------------
__device__ float g_q[N_E * HIDN];
__device__ float g_k[N_E * HIDN];
__device__ float g_v[N_E * HIDN];
__device__ float g_qcT[N_E * HIDN * NHD];  // [i][c][h]
__device__ float g_kcT[N_E * HIDN * NHD];  // [j][c][h]
__device__ float g_gate[N_E * NHD];
__device__ float g_scores[NHD * N_E * N_E];
__device__ float g_upd[N_E * HIDN];
__device__ float g_cpart[N_E * NHD * 3];
__device__ __nv_bfloat16 g_w2t_hi[HIDN * HIDN];  // [cout][cin]
__device__ __nv_bfloat16 g_w2t_lo[HIDN * HIDN];

// ---------------- helpers ----------------
__device__ __forceinline__ float silu_f(float x) {       // exact-ish (exp+rcp)
    return __fdividef(x, 1.0f + __expf(-x));
}
__device__ __forceinline__ float silu_t(float x) {       // tanh.approx (1 MUFU)
    float hx = 0.5f * x, t;
    asm("tanh.approx.f32 %0, %1;" : "=f"(t) : "f"(hx));
    return fmaf(hx, t, hx);
}
__device__ __forceinline__ float wsum(float v) {
#pragma unroll
    for (int o = 16; o; o >>= 1) v += __shfl_xor_sync(0xffffffffu, v, o);
    return v;
}
__device__ __forceinline__ float wmax(float v) {
#pragma unroll
    for (int o = 16; o; o >>= 1) v = fmaxf(v, __shfl_xor_sync(0xffffffffu, v, o));
    return v;
}
__device__ __forceinline__ uint32_t smem_u32(const void* p) {
    uint32_t a;
    asm("{ .reg .u64 t; cvta.to.shared.u64 t, %1; cvt.u32.u64 %0, t; }" : "=r"(a) : "l"(p));
    return a;
}
__device__ __forceinline__ void mma16816(float* c, const uint32_t* a, const uint32_t* b) {
    asm volatile(
        "mma.sync.aligned.m16n8k16.row.col.f32.bf16.bf16.f32 "
        "{%0,%1,%2,%3}, {%4,%5,%6,%7}, {%8,%9}, {%0,%1,%2,%3};"
        : "+f"(c[0]), "+f"(c[1]), "+f"(c[2]), "+f"(c[3])
        : "r"(a[0]), "r"(a[1]), "r"(a[2]), "r"(a[3]), "r"(b[0]), "r"(b[1]));
}
__device__ __forceinline__ void ldsm4(uint32_t* r, uint32_t addr) {
    asm volatile("ldmatrix.sync.aligned.m8n8.x4.shared.b16 {%0,%1,%2,%3}, [%4];"
                 : "=r"(r[0]), "=r"(r[1]), "=r"(r[2]), "=r"(r[3]) : "r"(addr));
}
// swizzled byte offset into a [rows x 256B] bf16 tile: XOR 16B-unit by (m&7)
__device__ __forceinline__ uint32_t swz(int m, int cbyte) {
    return (uint32_t)(m * 256 + (cbyte ^ ((m & 7) << 4)));
}

// ---------------- kernel 1: q,k,v projections ----------------
__global__ void k_qkv(const float* __restrict__ ef, const float* __restrict__ wq,
                      const float* __restrict__ wk, const float* __restrict__ wv) {
    int i = blockIdx.x, t = threadIdx.x;
    __shared__ float s_e[HIDN];
    s_e[t] = ef[i * HIDN + t];
    __syncthreads();
    float aq = 0.f, ak = 0.f, av = 0.f;
#pragma unroll 4
    for (int c = 0; c < HIDN; c++) {
        float e = s_e[c];
        aq += e * wq[c * HIDN + t];
        ak += e * wk[c * HIDN + t];
        av += e * wv[c * HIDN + t];
    }
    g_q[i * HIDN + t] = aq;
    g_k[i * HIDN + t] = ak;
    g_v[i * HIDN + t] = av;
}

// ---------------- kernel 2: qc/kc (transposed [edge][c][h]) ----------------
__global__ void k_qckc(const float* __restrict__ aw1) {
    int i = blockIdx.x, h = blockIdx.y, t = threadIdx.x;
    const float* qr = g_q + i * HIDN + h * DHD;
    const float* kr = g_k + i * HIDN + h * DHD;
    float aq = 0.f, ak = 0.f;
#pragma unroll
    for (int d = 0; d < DHD; d++) {
        aq += qr[d] * aw1[d * HIDN + t];
        ak += kr[d] * aw1[(DHD + d) * HIDN + t];
    }
    g_qcT[(i * HIDN + t) * NHD + h] = aq;
    g_kcT[(i * HIDN + t) * NHD + h] = ak;
}

// ---------------- kernel 3: gates ----------------
__global__ void k_gate(const float* __restrict__ gw1, const float* __restrict__ gb1,
                       const float* __restrict__ gw2, const float* __restrict__ gb2) {
    int i = blockIdx.x, h = blockIdx.y, t = threadIdx.x;
    int lane = t & 31, wid = t >> 5;
    const float* vr = g_v + i * HIDN + h * DHD;
    float acc = gb1[t];
#pragma unroll
    for (int d = 0; d < DHD; d++) acc += vr[d] * gw1[d * HIDN + t];
    float p = silu_f(acc) * gw2[t];
    p = wsum(p);
    __shared__ float sr[4];
    if (lane == 0) sr[wid] = p;
    __syncthreads();
    if (t == 0) {
        float s = sr[0] + sr[1] + sr[2] + sr[3] + gb2[0];
        g_gate[i * NHD + h] = __fdividef(1.0f, 1.0f + __expf(-s));
    }
}

// ---------------- kernel 3b: split w2^T into bf16 hi/lo ----------------
__global__ void k_w2t(const float* __restrict__ aw2) {
    int idx = blockIdx.x * 256 + threadIdx.x;  // 16384
    int cout = idx >> 7, cin = idx & 127;
    float w = aw2[cin * HIDN + cout];
    __nv_bfloat16 hi = __float2bfloat16_rn(w);
    float lo = w - __bfloat162float(hi);
    g_w2t_hi[idx] = hi;
    g_w2t_lo[idx] = __float2bfloat16_rn(lo);
}

// ---------------- kernel 4: persistent pair-MLP with HMMA bf16 ----------------
// smem byte map
#define A_HI_OFF 0          // 32768  [128 m][256B] swizzled bf16
#define A_LO_OFF 32768
#define B_HI_OFF 65536      // 32768  [128 n][256B] swizzled bf16
#define B_LO_OFF 98304
#define W1R_OFF 131072      // 8320 f (a_w1 rows 32..96)
#define QCT_OFF 164352      // 1024 f  [c][h]
#define RBFT_OFF 168448     // 65*16 f padded -> [r][p]
#define W3_OFF 172672       // 1024 f  [col*8+h]
#define B2_OFF 176768       // 128 f
#define AB3_OFF 177280      // 8 f
#define RC_OFF 177312       // 64 f
#define RW_OFF 177568       // 64 f
#define DIST_OFF 177824     // 16 f
#define SPART_OFF 177888    // 128 f
#define K4_SMEM_BYTES 178432

__global__ void __launch_bounds__(256, 1)
k_pair(const float* __restrict__ ec, const float* __restrict__ rc,
       const float* __restrict__ rw, const float* __restrict__ aw1,
       const float* __restrict__ ab1, const float* __restrict__ ab2,
       const float* __restrict__ aw3, const float* __restrict__ ab3,
       const float* __restrict__ mask) {
    extern __shared__ char sm[];
    const uint32_t sb = smem_u32(sm);
    float* s_w1r = (float*)(sm + W1R_OFF);
    float* s_qcT = (float*)(sm + QCT_OFF);
    float* s_rbfT = (float*)(sm + RBFT_OFF);
    float* s_w3 = (float*)(sm + W3_OFF);
    float* s_b2 = (float*)(sm + B2_OFF);
    float* s_ab3 = (float*)(sm + AB3_OFF);
    float* s_rc = (float*)(sm + RC_OFF);
    float* s_rw = (float*)(sm + RW_OFF);
    float* s_dist = (float*)(sm + DIST_OFF);
    float* s_part = (float*)(sm + SPART_OFF);

    int tid = threadIdx.x, lane = tid & 31, warp = tid >> 5;
    int gid = lane >> 2, tid4 = lane & 3;
    int wm = warp >> 2, wn = warp & 3;   // HMMA M-split(2) x N-split(4)
    int cpi = tid & 63, pg4 = tid >> 6;  // layer-1: c2 = 2*cpi, pairs pg4*4..+3
    int c2 = cpi * 2;

    // ---- one-time init ----
    for (int idx = tid; idx < 8320; idx += 256) s_w1r[idx] = aw1[32 * HIDN + idx];
    for (int idx = tid; idx < 1024; idx += 256) s_w3[idx] = aw3[idx];
    if (tid < 128) s_b2[tid] = ab2[tid];
    if (tid < 8) s_ab3[tid] = ab3[tid];
    if (tid < 64) {
        s_rc[tid] = rc[tid];
        s_rw[tid] = rw[tid];
    }
    // B tiles (w2^T hi/lo) into swizzled smem
    for (int idx = tid; idx < 2048; idx += 256) {
        int n = idx >> 4, k0 = (idx & 15) * 8;
        uint32_t off = swz(n, k0 * 2);
        *(uint4*)(sm + B_HI_OFF + off) = *(const uint4*)(g_w2t_hi + n * HIDN + k0);
        *(uint4*)(sm + B_LO_OFF + off) = *(const uint4*)(g_w2t_lo + n * HIDN + k0);
    }
    __syncthreads();

    for (int tile = blockIdx.x; tile < NTILES; tile += NBLK) {
        int i = tile / NJB;
        int j0 = (tile % NJB) * PAIRS;

        // ---- setup: qcT, dist/dot->rbfT row 64, zero s_part ----
        if (tid < 128) s_part[tid] = 0.f;
        *(float4*)(&s_qcT[tid * 4]) = *(const float4*)(&g_qcT[i * 1024 + tid * 4]);
        if (tid < PAIRS) {
            int j = j0 + tid;
            float ci0 = ec[i * 3], ci1 = ec[i * 3 + 1], ci2 = ec[i * 3 + 2];
            float cj0 = ec[j * 3], cj1 = ec[j * 3 + 1], cj2 = ec[j * 3 + 2];
            float dx = ci0 - cj0, dy = ci1 - cj1, dz = ci2 - cj2;
            float dist = sqrtf(dx * dx + dy * dy + dz * dz) + 1e-8f;
            dist = fminf(fmaxf(dist, 1e-8f), 1e8f);
            float dot = ci0 * cj0 + ci1 * cj1 + ci2 * cj2;
            dot = fminf(fmaxf(dot, -1e8f), 1e8f);
            s_dist[tid] = dist;
            s_rbfT[64 * 16 + tid] = dot;
        }
        __syncthreads();
        for (int t2 = tid; t2 < PAIRS * 64; t2 += 256) {
            int p = t2 & 15, r = t2 >> 4;
            float d = s_dist[p];
            float dd = d - s_rc[r];
            s_rbfT[r * 16 + p] = (d <= 10.0f) ? __expf(-s_rw[r] * dd * dd) : 0.0f;
        }
        __syncthreads();

        // ---- layer-1 base: acc[c'][p] = sum_r rbfT[r][p] * w1r[r][c2+c'] (+bias) ----
        {
            float bias0 = ab1[c2], bias1 = ab1[c2 + 1];
            float accb[2][4];
#pragma unroll
            for (int p = 0; p < 4; p++) {
                accb[0][p] = bias0;
                accb[1][p] = bias1;
            }
#pragma unroll 5
            for (int r = 0; r < 65; r++) {
                float2 w = *(const float2*)(&s_w1r[r * HIDN + c2]);
                float4 rb = *(const float4*)(&s_rbfT[r * 16 + pg4 * 4]);
                accb[0][0] += rb.x * w.x; accb[1][0] += rb.x * w.y;
                accb[0][1] += rb.y * w.x; accb[1][1] += rb.y * w.y;
                accb[0][2] += rb.z * w.x; accb[1][2] += rb.z * w.y;
                accb[0][3] += rb.w * w.x; accb[1][3] += rb.w * w.y;
            }

            // qc for this thread's two c's
            float qv0[8], qv1[8];
            *(float4*)(qv0) = *(const float4*)(&s_qcT[c2 * 8]);
            *(float4*)(qv0 + 4) = *(const float4*)(&s_qcT[c2 * 8 + 4]);
            *(float4*)(qv1) = *(const float4*)(&s_qcT[c2 * 8 + 8]);
            *(float4*)(qv1 + 4) = *(const float4*)(&s_qcT[c2 * 8 + 12]);

            // heads: x = silu(base + qc + kc) -> A_hi/A_lo (packed bf16x2 stores)
#pragma unroll
            for (int pp = 0; pp < 4; pp++) {
                int j = j0 + pg4 * 4 + pp;
                const float* kcp = g_kcT + (j * HIDN + c2) * 8;
                float kc0[8], kc1[8];
                *(float4*)(kc0) = *(const float4*)(kcp);
                *(float4*)(kc0 + 4) = *(const float4*)(kcp + 4);
                *(float4*)(kc1) = *(const float4*)(kcp + 8);
                *(float4*)(kc1 + 4) = *(const float4*)(kcp + 12);
                int m_base = pg4 * 4 + pp;
#pragma unroll
                for (int h = 0; h < NHD; h++) {
                    float x0 = silu_t(accb[0][pp] + qv0[h] + kc0[h]);
                    float x1 = silu_t(accb[1][pp] + qv1[h] + kc1[h]);
                    __nv_bfloat16 h0 = __float2bfloat16_rn(x0);
                    __nv_bfloat16 h1 = __float2bfloat16_rn(x1);
                    __nv_bfloat16 l0 = __float2bfloat16_rn(x0 - __bfloat162float(h0));
                    __nv_bfloat16 l1 = __float2bfloat16_rn(x1 - __bfloat162float(h1));
                    uint32_t hp = (uint32_t)*(uint16_t*)&h0 | ((uint32_t)*(uint16_t*)&h1 << 16);
                    uint32_t lp = (uint32_t)*(uint16_t*)&l0 | ((uint32_t)*(uint16_t*)&l1 << 16);
                    int m = h * PAIRS + m_base;
                    uint32_t off = swz(m, c2 * 2);
                    *(uint32_t*)(sm + A_HI_OFF + off) = hp;
                    *(uint32_t*)(sm + A_LO_OFF + off) = lp;
                }
            }
        }
        __syncthreads();

        // ---- HMMA: D = Ahi*Bhi + Alo*Bhi + Ahi*Blo; warp = (wm, wn) ----
        float acc[4][4][4];
#pragma unroll
        for (int mb = 0; mb < 4; mb++)
#pragma unroll
            for (int nb = 0; nb < 4; nb++)
#pragma unroll
                for (int q = 0; q < 4; q++) acc[mb][nb][q] = 0.f;

        // lane addressing for ldmatrix
        int a_row = (lane & 7) + ((lane >> 3) & 1) * 8;
        int a_kh = (lane >> 4) & 1;
        int b_row = wn * 32 + ((lane >> 4) & 1) * 8 + (lane & 7);
        int b_kh = (lane >> 3) & 1;

#pragma unroll
        for (int kb = 0; kb < 8; kb++) {
            uint32_t bh[4][2], bl[4][2];
#pragma unroll
            for (int nb2 = 0; nb2 < 2; nb2++) {
                uint32_t boff = swz(b_row + nb2 * 16, kb * 32 + b_kh * 16);
                uint32_t rr[4];
                ldsm4(rr, sb + B_HI_OFF + boff);
                bh[nb2 * 2][0] = rr[0]; bh[nb2 * 2][1] = rr[1];
                bh[nb2 * 2 + 1][0] = rr[2]; bh[nb2 * 2 + 1][1] = rr[3];
                ldsm4(rr, sb + B_LO_OFF + boff);
                bl[nb2 * 2][0] = rr[0]; bl[nb2 * 2][1] = rr[1];
                bl[nb2 * 2 + 1][0] = rr[2]; bl[nb2 * 2 + 1][1] = rr[3];
            }
#pragma unroll
            for (int mb = 0; mb < 4; mb++) {
                uint32_t aoff = swz(wm * 64 + mb * 16 + a_row, kb * 32 + a_kh * 16);
                uint32_t ahi[4], alo[4];
                ldsm4(ahi, sb + A_HI_OFF + aoff);
                ldsm4(alo, sb + A_LO_OFF + aoff);
#pragma unroll
                for (int nb = 0; nb < 4; nb++) {
                    mma16816(acc[mb][nb], ahi, bh[nb]);
                    mma16816(acc[mb][nb], alo, bh[nb]);
                    mma16816(acc[mb][nb], ahi, bl[nb]);
                }
            }
        }

        // ---- epilogue: silu(D + b2) . w3[:,h], reduce into s_part[m] ----
#pragma unroll
        for (int mb = 0; mb < 4; mb++) {
            int h = wm * 4 + mb;
            float p0 = 0.f, p1 = 0.f;
#pragma unroll
            for (int nb = 0; nb < 4; nb++) {
                int c0 = wn * 32 + nb * 8 + tid4 * 2;
                float w30 = s_w3[c0 * NHD + h], w31 = s_w3[(c0 + 1) * NHD + h];
                float b20 = s_b2[c0], b21 = s_b2[c0 + 1];
                p0 += silu_f(acc[mb][nb][0] + b20) * w30 + silu_f(acc[mb][nb][1] + b21) * w31;
                p1 += silu_f(acc[mb][nb][2] + b20) * w30 + silu_f(acc[mb][nb][3] + b21) * w31;
            }
            p0 += __shfl_xor_sync(0xffffffffu, p0, 1);
            p0 += __shfl_xor_sync(0xffffffffu, p0, 2);
            p1 += __shfl_xor_sync(0xffffffffu, p1, 1);
            p1 += __shfl_xor_sync(0xffffffffu, p1, 2);
            if (tid4 == 0) {
                int m = wm * 64 + mb * 16 + gid;
                atomicAdd(&s_part[m], p0);
                atomicAdd(&s_part[m + 8], p1);
            }
        }
        __syncthreads();

        if (tid < 128) {
            int h = tid >> 4, p = tid & 15;
            int j = j0 + p;
            float s = s_part[tid] + s_ab3[h] + mask[i * N_E + j];
            s = fminf(fmaxf(s, -1e9f), 1e9f);
            g_scores[(h * N_E + i) * N_E + j] = s;
        }
        __syncthreads();
    }
}

// ---------------- kernel 5: softmax + feats + coord partials ----------------
__global__ void k_soft(const float* __restrict__ ec) {
    int i = blockIdx.x, h = blockIdx.y;
    int tid = threadIdx.x, lane = tid & 31, wid = tid >> 5;
    int j = tid;
    __shared__ float s_r[12];
    __shared__ float s_feat[12 * 16];
    __shared__ float s_c[12 * 3];
    __shared__ float s_b;

    float sc = g_scores[(h * N_E + i) * N_E + j];
    float m = wmax(sc);
    if (lane == 0) s_r[wid] = m;
    __syncthreads();
    if (tid == 0) {
        float mm = s_r[0];
        for (int w = 1; w < 12; w++) mm = fmaxf(mm, s_r[w]);
        s_b = mm;
    }
    __syncthreads();
    float e = __expf(sc - s_b);
    float su = wsum(e);
    if (lane == 0) s_r[wid] = su;
    __syncthreads();
    if (tid == 0) {
        float ss = 0.f;
        for (int w = 0; w < 12; w++) ss += s_r[w];
        s_b = ss;
    }
    __syncthreads();
    float attn = __fdividef(e, s_b);

    float part[16];
    const float* vrow = g_v + j * HIDN + h * DHD;
#pragma unroll
    for (int d = 0; d < 16; d++) part[d] = attn * vrow[d];
#pragma unroll
    for (int d = 0; d < 16; d++) part[d] = wsum(part[d]);
    if (lane == 0) {
#pragma unroll
        for (int d = 0; d < 16; d++) s_feat[wid * 16 + d] = part[d];
    }

    float ga = g_gate[i * NHD + h] * attn;
    float cv[3];
    cv[0] = ga * (ec[i * 3 + 0] - ec[j * 3 + 0]);
    cv[1] = ga * (ec[i * 3 + 1] - ec[j * 3 + 1]);
    cv[2] = ga * (ec[i * 3 + 2] - ec[j * 3 + 2]);
#pragma unroll
    for (int d = 0; d < 3; d++) {
        float v = wsum(cv[d]);
        if (lane == 0) s_c[wid * 3 + d] = v;
    }
    __syncthreads();
    if (tid < 16) {
        float a = 0.f;
        for (int w = 0; w < 12; w++) a += s_feat[w * 16 + tid];
        g_upd[i * HIDN + h * DHD + tid] = a;
    }
    if (tid >= 32 && tid < 35) {
        int d = tid - 32;
        float a = 0.f;
        for (int w = 0; w < 12; w++) a += s_c[w * 3 + d];
        g_cpart[(i * NHD + h) * 3 + d] = a;
    }
}

// ---------------- kernel 6: output proj + layernorm + coords ----------------
__global__ void k_out(const float* __restrict__ ef, const float* __restrict__ wo,
                      const float* __restrict__ bo, const float* __restrict__ lng,
                      const float* __restrict__ lnb, const float* __restrict__ ec,
                      float* __restrict__ out) {
    int i = blockIdx.x, t = threadIdx.x, lane = t & 31, wid = t >> 5;
    __shared__ float s_u[HIDN];
    __shared__ float s_r[4];
    __shared__ float s_b;
    s_u[t] = g_upd[i * HIDN + t];
    __syncthreads();
    float acc = ef[i * HIDN + t] + bo[t];
#pragma unroll 4
    for (int c = 0; c < HIDN; c++) acc += s_u[c] * wo[c * HIDN + t];
    float m = wsum(acc);
    if (lane == 0) s_r[wid] = m;
    __syncthreads();
    if (t == 0) s_b = (s_r[0] + s_r[1] + s_r[2] + s_r[3]) * (1.0f / 128.0f);
    __syncthreads();
    float mu = s_b;
    float d = acc - mu;
    float v = wsum(d * d);
    __syncthreads();
    if (lane == 0) s_r[wid] = v;
    __syncthreads();
    if (t == 0) s_b = (s_r[0] + s_r[1] + s_r[2] + s_r[3]) * (1.0f / 128.0f);
    __syncthreads();
    out[i * HIDN + t] = d * rsqrtf(s_b + 1e-5f) * lng[t] + lnb[t];
    if (t < 3) {
        float a = 0.f;
#pragma unroll
        for (int h = 0; h < NHD; h++) a += g_cpart[(i * NHD + h) * 3 + t];
        out[N_E * HIDN + i * 3 + t] = ec[i * 3 + t] + a * 0.125f;
    }
}

// ---------------- launch ----------------
extern "C" void kernel_launch(void* const* d_in, const int* in_sizes, int n_in,
                              void* d_out, int out_size) {
    const float* ef = (const float*)d_in[0];
    const float* ec = (const float*)d_in[1];
    const float* mask = (const float*)d_in[2];
    const float* wq = (const float*)d_in[3];
    const float* wk = (const float*)d_in[4];
    const float* wv = (const float*)d_in[5];
    const float* rc = (const float*)d_in[6];
    const float* rw = (const float*)d_in[7];
    const float* aw1 = (const float*)d_in[8];
    const float* ab1 = (const float*)d_in[9];
    const float* aw2 = (const float*)d_in[10];
    const float* ab2 = (const float*)d_in[11];
    const float* aw3 = (const float*)d_in[12];
    const float* ab3 = (const float*)d_in[13];
    const float* gw1 = (const float*)d_in[14];
    const float* gb1 = (const float*)d_in[15];
    const float* gw2 = (const float*)d_in[16];
    const float* gb2 = (const float*)d_in[17];
    const float* wo = (const float*)d_in[18];
    const float* bo = (const float*)d_in[19];
    const float* lng = (const float*)d_in[20];
    const float* lnb = (const float*)d_in[21];
    float* out = (float*)d_out;

    // order chosen so the ncu capture slot lands on k_pair
    k_qkv<<<N_E, 128>>>(ef, wq, wk, wv);
    k_qckc<<<dim3(N_E, NHD), 128>>>(aw1);
    k_w2t<<<64, 256>>>(aw2);

    cudaFuncSetAttribute(k_pair, cudaFuncAttributeMaxDynamicSharedMemorySize, K4_SMEM_BYTES);
    k_pair<<<NBLK, 256, K4_SMEM_BYTES>>>(ec, rc, rw, aw1, ab1, ab2, aw3, ab3, mask);

    k_gate<<<dim3(N_E, NHD), 128>>>(gw1, gb1, gw2, gb2);
    k_soft<<<dim3(N_E, NHD), N_E>>>(ec);
    k_out<<<N_E, 128>>>(ef, wo, bo, lng, lnb, ec, out);
}

// round 7
// speedup vs baseline: 3.5419x; 1.2697x over previous
#include <cuda_runtime.h>
#include <cuda_bf16.h>
#include <cstdint>

#define N_E 384
#define HIDN 128
#define NHD 8
#define DHD 16
#define PAIRS 16
#define NJB (N_E / PAIRS)     // 24
#define NTILES (N_E * NJB)    // 9216
#define NBLK 148

typedef unsigned long long ull;

// ---------------- scratch ----------------
__device__ float g_q[N_E * HIDN];
__device__ float g_k[N_E * HIDN];
__device__ float g_v[N_E * HIDN];
__device__ float g_qcT[N_E * HIDN * NHD];  // [i][c][h]
__device__ float g_kcT[N_E * HIDN * NHD];  // [j][c][h]
__device__ float g_gate[N_E * NHD];
__device__ float g_scores[NHD * N_E * N_E];
__device__ float g_upd[N_E * HIDN];
__device__ float g_cpart[N_E * NHD * 3];
__device__ __nv_bfloat16 g_w2t_hi[HIDN * HIDN];  // [cout][cin]
__device__ __nv_bfloat16 g_w2t_lo[HIDN * HIDN];
__device__ __nv_bfloat16 g_w1b_hi[HIDN * HIDN];  // [c][k] k: 0..64 rbf/dot, 65 bias, rest 0
__device__ __nv_bfloat16 g_w1b_lo[HIDN * HIDN];

// ---------------- helpers ----------------
__device__ __forceinline__ float silu_f(float x) {
    return __fdividef(x, 1.0f + __expf(-x));
}
__device__ __forceinline__ float silu_t(float x) {  // tanh-based, 1 MUFU
    float hx = 0.5f * x, t;
    asm("tanh.approx.f32 %0, %1;" : "=f"(t) : "f"(hx));
    return fmaf(hx, t, hx);
}
__device__ __forceinline__ float wsum(float v) {
#pragma unroll
    for (int o = 16; o; o >>= 1) v += __shfl_xor_sync(0xffffffffu, v, o);
    return v;
}
__device__ __forceinline__ float wmax(float v) {
#pragma unroll
    for (int o = 16; o; o >>= 1) v = fmaxf(v, __shfl_xor_sync(0xffffffffu, v, o));
    return v;
}
__device__ __forceinline__ uint32_t smem_u32(const void* p) {
    uint32_t a;
    asm("{ .reg .u64 t; cvta.to.shared.u64 t, %1; cvt.u32.u64 %0, t; }" : "=r"(a) : "l"(p));
    return a;
}
__device__ __forceinline__ void mma16816(float* c, const uint32_t* a, const uint32_t* b) {
    asm volatile(
        "mma.sync.aligned.m16n8k16.row.col.f32.bf16.bf16.f32 "
        "{%0,%1,%2,%3}, {%4,%5,%6,%7}, {%8,%9}, {%0,%1,%2,%3};"
        : "+f"(c[0]), "+f"(c[1]), "+f"(c[2]), "+f"(c[3])
        : "r"(a[0]), "r"(a[1]), "r"(a[2]), "r"(a[3]), "r"(b[0]), "r"(b[1]));
}
__device__ __forceinline__ void ldsm4(uint32_t* r, uint32_t addr) {
    asm volatile("ldmatrix.sync.aligned.m8n8.x4.shared.b16 {%0,%1,%2,%3}, [%4];"
                 : "=r"(r[0]), "=r"(r[1]), "=r"(r[2]), "=r"(r[3]) : "r"(addr));
}
// swizzled byte offset into a [rows x 256B] bf16 tile
__device__ __forceinline__ uint32_t swz(int m, int cbyte) {
    return (uint32_t)(m * 256 + (cbyte ^ ((m & 7) << 4)));
}
// pack two floats to bf16x2 (lo -> low half, hi -> high half)
__device__ __forceinline__ uint32_t pack_bf16x2(float lo, float hi) {
    uint32_t r;
    asm("cvt.rn.bf16x2.f32 %0, %1, %2;" : "=r"(r) : "f"(hi), "f"(lo));
    return r;
}

// ---------------- kernel 1: q,k,v projections ----------------
__global__ void k_qkv(const float* __restrict__ ef, const float* __restrict__ wq,
                      const float* __restrict__ wk, const float* __restrict__ wv) {
    int i = blockIdx.x, t = threadIdx.x;
    __shared__ float s_e[HIDN];
    s_e[t] = ef[i * HIDN + t];
    __syncthreads();
    float aq = 0.f, ak = 0.f, av = 0.f;
#pragma unroll 4
    for (int c = 0; c < HIDN; c++) {
        float e = s_e[c];
        aq += e * wq[c * HIDN + t];
        ak += e * wk[c * HIDN + t];
        av += e * wv[c * HIDN + t];
    }
    g_q[i * HIDN + t] = aq;
    g_k[i * HIDN + t] = ak;
    g_v[i * HIDN + t] = av;
}

// ---------------- kernel 2: qc/kc (transposed [edge][c][h]) ----------------
__global__ void k_qckc(const float* __restrict__ aw1) {
    int i = blockIdx.x, h = blockIdx.y, t = threadIdx.x;
    const float* qr = g_q + i * HIDN + h * DHD;
    const float* kr = g_k + i * HIDN + h * DHD;
    float aq = 0.f, ak = 0.f;
#pragma unroll
    for (int d = 0; d < DHD; d++) {
        aq += qr[d] * aw1[d * HIDN + t];
        ak += kr[d] * aw1[(DHD + d) * HIDN + t];
    }
    g_qcT[(i * HIDN + t) * NHD + h] = aq;
    g_kcT[(i * HIDN + t) * NHD + h] = ak;
}

// ---------------- kernel 3: gates ----------------
__global__ void k_gate(const float* __restrict__ gw1, const float* __restrict__ gb1,
                       const float* __restrict__ gw2, const float* __restrict__ gb2) {
    int i = blockIdx.x, h = blockIdx.y, t = threadIdx.x;
    int lane = t & 31, wid = t >> 5;
    const float* vr = g_v + i * HIDN + h * DHD;
    float acc = gb1[t];
#pragma unroll
    for (int d = 0; d < DHD; d++) acc += vr[d] * gw1[d * HIDN + t];
    float p = silu_f(acc) * gw2[t];
    p = wsum(p);
    __shared__ float sr[4];
    if (lane == 0) sr[wid] = p;
    __syncthreads();
    if (t == 0) {
        float s = sr[0] + sr[1] + sr[2] + sr[3] + gb2[0];
        g_gate[i * NHD + h] = __fdividef(1.0f, 1.0f + __expf(-s));
    }
}

// ---------------- kernel 3b: split w2^T into bf16 hi/lo ----------------
__global__ void k_w2t(const float* __restrict__ aw2) {
    int idx = blockIdx.x * 256 + threadIdx.x;  // 16384
    int cout = idx >> 7, cin = idx & 127;
    float w = aw2[cin * HIDN + cout];
    __nv_bfloat16 hi = __float2bfloat16_rn(w);
    float lo = w - __bfloat162float(hi);
    g_w2t_hi[idx] = hi;
    g_w2t_lo[idx] = __float2bfloat16_rn(lo);
}

// ---------------- kernel 3c: w1 geometric block as B-matrix [c][k] hi/lo ----------------
__global__ void k_w1rb(const float* __restrict__ aw1, const float* __restrict__ ab1) {
    int idx = blockIdx.x * 256 + threadIdx.x;  // 16384
    int c = idx >> 7, k = idx & 127;
    float w = 0.f;
    if (k < 65) w = aw1[(32 + k) * HIDN + c];      // rbf rows 32..95, dot row 96
    else if (k == 65) w = ab1[c];                  // bias via constant-1 rbf col
    __nv_bfloat16 hi = __float2bfloat16_rn(w);
    float lo = w - __bfloat162float(hi);
    g_w1b_hi[idx] = hi;
    g_w1b_lo[idx] = __float2bfloat16_rn(lo);
}

// ---------------- kernel 4: persistent pair-MLP, all GEMMs on HMMA ----------------
// smem byte map
#define A_HI_OFF 0          // 32768 [128 m][256B]
#define A_LO_OFF 32768
#define B_HI_OFF 65536      // 32768 w2^T
#define B_LO_OFF 98304
#define W1B_HI_OFF 131072   // 32768 [c][256B]
#define W1B_LO_OFF 163840
#define RBF_HI_OFF 196608   // 4096 [16 p][256B]
#define RBF_LO_OFF 200704
#define BASE_OFF 204800     // 8192 f32 [16 p][128 c]
#define QCT_OFF 212992      // 4096 f32 [c][h]
#define W3T_OFF 217088      // 4096 f32 [h][c]
#define AB3_OFF 221184      // 32
#define RC_OFF 221216       // 256
#define RW_OFF 221472       // 256
#define SPART_OFF 221728    // 512
#define K4_SMEM_BYTES 222240

__global__ void __launch_bounds__(256, 1)
k_pair(const float* __restrict__ ec, const float* __restrict__ rc,
       const float* __restrict__ rw, const float* __restrict__ ab2,
       const float* __restrict__ aw3, const float* __restrict__ ab3,
       const float* __restrict__ mask) {
    extern __shared__ char sm[];
    const uint32_t sb = smem_u32(sm);
    float* s_base = (float*)(sm + BASE_OFF);
    float* s_qcT = (float*)(sm + QCT_OFF);
    float* s_w3T = (float*)(sm + W3T_OFF);
    float* s_ab3 = (float*)(sm + AB3_OFF);
    float* s_rc = (float*)(sm + RC_OFF);
    float* s_rw = (float*)(sm + RW_OFF);
    float* s_part = (float*)(sm + SPART_OFF);

    int tid = threadIdx.x, lane = tid & 31, warp = tid >> 5;
    int gid = lane >> 2, tid4 = lane & 3;
    int wm = warp >> 2, wn = warp & 3;   // main MMA: M-split 2 x N-split 4
    int cpi = tid & 63, pg4 = tid >> 6;  // silu stage: c2 = 2*cpi, pairs pg4*4..+3
    int c2 = cpi * 2;

    // ---- one-time init ----
    for (int idx = tid; idx < 1024; idx += 256) {
        int h = idx >> 7, c = idx & 127;
        s_w3T[idx] = aw3[c * NHD + h];
    }
    if (tid < 8) s_ab3[tid] = ab3[tid];
    if (tid < 64) {
        s_rc[tid] = rc[tid];
        s_rw[tid] = rw[tid];
    }
    // B tiles (w2^T hi/lo) and w1b tiles into swizzled smem
    for (int idx = tid; idx < 2048; idx += 256) {
        int n = idx >> 4, k0 = (idx & 15) * 8;
        uint32_t off = swz(n, k0 * 2);
        *(uint4*)(sm + B_HI_OFF + off) = *(const uint4*)(g_w2t_hi + n * HIDN + k0);
        *(uint4*)(sm + B_LO_OFF + off) = *(const uint4*)(g_w2t_lo + n * HIDN + k0);
        *(uint4*)(sm + W1B_HI_OFF + off) = *(const uint4*)(g_w1b_hi + n * HIDN + k0);
        *(uint4*)(sm + W1B_LO_OFF + off) = *(const uint4*)(g_w1b_lo + n * HIDN + k0);
    }
    // zero rbf tiles, then set constant-1 column (k=65 -> bytes 130)
    for (int idx = tid; idx < 1024; idx += 256) {
        ((uint32_t*)(sm + RBF_HI_OFF))[idx] = 0;
        ((uint32_t*)(sm + RBF_LO_OFF))[idx] = 0;
    }
    __syncthreads();
    if (tid < 16) {
        *(uint16_t*)(sm + RBF_HI_OFF + swz(tid, 130)) = 0x3F80;  // bf16(1.0)
    }
    // epilogue constants hoisted to registers
    float b2r[8];
#pragma unroll
    for (int nb = 0; nb < 4; nb++) {
        int c0 = wn * 32 + nb * 8 + tid4 * 2;
        b2r[nb * 2] = ab2[c0];
        b2r[nb * 2 + 1] = ab2[c0 + 1];
    }
    __syncthreads();

    // ldmatrix lane addressing (shared by base + main GEMMs)
    int a_row = lane & 15;
    int a_kh = (lane >> 4) & 1;
    int b_row_main = wn * 32 + ((lane >> 4) & 1) * 8 + (lane & 7);
    int b_row_base = warp * 16 + ((lane >> 4) & 1) * 8 + (lane & 7);
    int b_kh = (lane >> 3) & 1;

    for (int tile = blockIdx.x; tile < NTILES; tile += NBLK) {
        int i = tile / NJB;
        int j0 = (tile % NJB) * PAIRS;

        // ---- phase 1: rbf + dot into A_rbf tiles; qcT; zero s_part ----
        if (tid < 128) s_part[tid] = 0.f;
        *(float4*)(&s_qcT[tid * 4]) = *(const float4*)(&g_qcT[i * 1024 + tid * 4]);
        float ci0 = ec[i * 3], ci1 = ec[i * 3 + 1], ci2 = ec[i * 3 + 2];
#pragma unroll
        for (int it = 0; it < 2; it++) {
            int idx = tid + it * 256;     // 0..511
            int p = idx & 15, rq = idx >> 4;  // rq 0..31 -> r = 2rq, 2rq+1
            int j = j0 + p;
            float cj0 = ec[j * 3], cj1 = ec[j * 3 + 1], cj2 = ec[j * 3 + 2];
            float dx = ci0 - cj0, dy = ci1 - cj1, dz = ci2 - cj2;
            float dist = sqrtf(dx * dx + dy * dy + dz * dz) + 1e-8f;
            dist = fminf(fmaxf(dist, 1e-8f), 1e8f);
            int r0 = rq * 2, r1 = r0 + 1;
            float d0 = dist - s_rc[r0], d1 = dist - s_rc[r1];
            float v0 = (dist <= 10.0f) ? __expf(-s_rw[r0] * d0 * d0) : 0.0f;
            float v1 = (dist <= 10.0f) ? __expf(-s_rw[r1] * d1 * d1) : 0.0f;
            uint32_t hp = pack_bf16x2(v0, v1);
            float e0 = v0 - __uint_as_float(hp << 16);
            float e1 = v1 - __uint_as_float(hp & 0xFFFF0000u);
            uint32_t lp = pack_bf16x2(e0, e1);
            uint32_t off = swz(p, rq * 4);
            *(uint32_t*)(sm + RBF_HI_OFF + off) = hp;
            *(uint32_t*)(sm + RBF_LO_OFF + off) = lp;
        }
        if (tid < 16) {
            int j = j0 + tid;
            float cj0 = ec[j * 3], cj1 = ec[j * 3 + 1], cj2 = ec[j * 3 + 2];
            float dot = ci0 * cj0 + ci1 * cj1 + ci2 * cj2;
            dot = fminf(fmaxf(dot, -1e8f), 1e8f);
            __nv_bfloat16 dh = __float2bfloat16_rn(dot);
            __nv_bfloat16 dl = __float2bfloat16_rn(dot - __bfloat162float(dh));
            uint32_t off = swz(tid, 128);
            *(uint16_t*)(sm + RBF_HI_OFF + off) = *(uint16_t*)&dh;
            *(uint16_t*)(sm + RBF_LO_OFF + off) = *(uint16_t*)&dl;
        }
        __syncthreads();

        // ---- phase 2: base GEMM (16 x 128, K eff 66) ; warp owns 16 couts ----
        {
            float bacc[2][4];
#pragma unroll
            for (int nb = 0; nb < 2; nb++)
#pragma unroll
                for (int q = 0; q < 4; q++) bacc[nb][q] = 0.f;
#pragma unroll
            for (int kb = 0; kb < 5; kb++) {   // K 0..79 covers cols 0..65
                uint32_t rhi[4], rlo[4];
                ldsm4(rhi, sb + RBF_HI_OFF + swz(a_row, kb * 32 + a_kh * 16));
                ldsm4(rlo, sb + RBF_LO_OFF + swz(a_row, kb * 32 + a_kh * 16));
                uint32_t boff = swz(b_row_base, kb * 32 + b_kh * 16);
                uint32_t rr[4];
                uint32_t wh[2][2], wl[2][2];
                ldsm4(rr, sb + W1B_HI_OFF + boff);
                wh[0][0] = rr[0]; wh[0][1] = rr[1]; wh[1][0] = rr[2]; wh[1][1] = rr[3];
                ldsm4(rr, sb + W1B_LO_OFF + boff);
                wl[0][0] = rr[0]; wl[0][1] = rr[1]; wl[1][0] = rr[2]; wl[1][1] = rr[3];
#pragma unroll
                for (int nb = 0; nb < 2; nb++) {
                    mma16816(bacc[nb], rhi, wh[nb]);
                    mma16816(bacc[nb], rlo, wh[nb]);
                    mma16816(bacc[nb], rhi, wl[nb]);
                }
            }
#pragma unroll
            for (int nb = 0; nb < 2; nb++) {
                int c0 = warp * 16 + nb * 8 + tid4 * 2;
                float2 v0 = {bacc[nb][0], bacc[nb][1]};
                float2 v1 = {bacc[nb][2], bacc[nb][3]};
                *(float2*)(&s_base[gid * 128 + c0]) = v0;
                *(float2*)(&s_base[(gid + 8) * 128 + c0]) = v1;
            }
        }
        __syncthreads();

        // ---- phase 3: x1 = silu(base + qc + kc) -> A_hi/A_lo ----
        {
            float qv0[8], qv1[8];
            *(float4*)(qv0) = *(const float4*)(&s_qcT[c2 * 8]);
            *(float4*)(qv0 + 4) = *(const float4*)(&s_qcT[c2 * 8 + 4]);
            *(float4*)(qv1) = *(const float4*)(&s_qcT[c2 * 8 + 8]);
            *(float4*)(qv1 + 4) = *(const float4*)(&s_qcT[c2 * 8 + 12]);
#pragma unroll
            for (int pp = 0; pp < 4; pp++) {
                int p = pg4 * 4 + pp;
                int j = j0 + p;
                float2 bs = *(const float2*)(&s_base[p * 128 + c2]);
                const float* kcp = g_kcT + (j * HIDN + c2) * 8;
                float kc0[8], kc1[8];
                *(float4*)(kc0) = *(const float4*)(kcp);
                *(float4*)(kc0 + 4) = *(const float4*)(kcp + 4);
                *(float4*)(kc1) = *(const float4*)(kcp + 8);
                *(float4*)(kc1 + 4) = *(const float4*)(kcp + 12);
#pragma unroll
                for (int h = 0; h < NHD; h++) {
                    float x0 = silu_t(bs.x + qv0[h] + kc0[h]);
                    float x1 = silu_t(bs.y + qv1[h] + kc1[h]);
                    uint32_t hp = pack_bf16x2(x0, x1);
                    float r0 = x0 - __uint_as_float(hp << 16);
                    float r1 = x1 - __uint_as_float(hp & 0xFFFF0000u);
                    uint32_t lp = pack_bf16x2(r0, r1);
                    int m = h * PAIRS + p;
                    uint32_t off = swz(m, c2 * 2);
                    *(uint32_t*)(sm + A_HI_OFF + off) = hp;
                    *(uint32_t*)(sm + A_LO_OFF + off) = lp;
                }
            }
        }
        __syncthreads();

        // ---- phase 4: main GEMM D = Ahi*Bhi + Alo*Bhi + Ahi*Blo ----
        float acc[4][4][4];
#pragma unroll
        for (int mb = 0; mb < 4; mb++)
#pragma unroll
            for (int nb = 0; nb < 4; nb++)
#pragma unroll
                for (int q = 0; q < 4; q++) acc[mb][nb][q] = 0.f;

#pragma unroll
        for (int kb = 0; kb < 8; kb++) {
            uint32_t bh[4][2], bl[4][2];
#pragma unroll
            for (int nb2 = 0; nb2 < 2; nb2++) {
                uint32_t boff = swz(b_row_main + nb2 * 16, kb * 32 + b_kh * 16);
                uint32_t rr[4];
                ldsm4(rr, sb + B_HI_OFF + boff);
                bh[nb2 * 2][0] = rr[0]; bh[nb2 * 2][1] = rr[1];
                bh[nb2 * 2 + 1][0] = rr[2]; bh[nb2 * 2 + 1][1] = rr[3];
                ldsm4(rr, sb + B_LO_OFF + boff);
                bl[nb2 * 2][0] = rr[0]; bl[nb2 * 2][1] = rr[1];
                bl[nb2 * 2 + 1][0] = rr[2]; bl[nb2 * 2 + 1][1] = rr[3];
            }
#pragma unroll
            for (int mb = 0; mb < 4; mb++) {
                uint32_t aoff = swz(wm * 64 + mb * 16 + a_row, kb * 32 + a_kh * 16);
                uint32_t ahi[4], alo[4];
                ldsm4(ahi, sb + A_HI_OFF + aoff);
                ldsm4(alo, sb + A_LO_OFF + aoff);
#pragma unroll
                for (int nb = 0; nb < 4; nb++) {
                    mma16816(acc[mb][nb], ahi, bh[nb]);
                    mma16816(acc[mb][nb], alo, bh[nb]);
                    mma16816(acc[mb][nb], ahi, bl[nb]);
                }
            }
        }

        // ---- phase 5: epilogue silu(D+b2).w3 -> s_part ----
#pragma unroll
        for (int mb = 0; mb < 4; mb++) {
            int h = wm * 4 + mb;
            float p0 = 0.f, p1 = 0.f;
#pragma unroll
            for (int nb = 0; nb < 4; nb++) {
                int c0 = wn * 32 + nb * 8 + tid4 * 2;
                float2 w3v = *(const float2*)(&s_w3T[h * 128 + c0]);
                p0 += silu_t(acc[mb][nb][0] + b2r[nb * 2]) * w3v.x +
                      silu_t(acc[mb][nb][1] + b2r[nb * 2 + 1]) * w3v.y;
                p1 += silu_t(acc[mb][nb][2] + b2r[nb * 2]) * w3v.x +
                      silu_t(acc[mb][nb][3] + b2r[nb * 2 + 1]) * w3v.y;
            }
            p0 += __shfl_xor_sync(0xffffffffu, p0, 1);
            p0 += __shfl_xor_sync(0xffffffffu, p0, 2);
            p1 += __shfl_xor_sync(0xffffffffu, p1, 1);
            p1 += __shfl_xor_sync(0xffffffffu, p1, 2);
            if (tid4 == 0) {
                int m = wm * 64 + mb * 16 + gid;
                atomicAdd(&s_part[m], p0);
                atomicAdd(&s_part[m + 8], p1);
            }
        }
        __syncthreads();

        if (tid < 128) {
            int h = tid >> 4, p = tid & 15;
            int j = j0 + p;
            float s = s_part[tid] + s_ab3[h] + mask[i * N_E + j];
            s = fminf(fmaxf(s, -1e9f), 1e9f);
            g_scores[(h * N_E + i) * N_E + j] = s;
        }
        __syncthreads();
    }
}

// ---------------- kernel 5: softmax + feats + coord partials ----------------
__global__ void k_soft(const float* __restrict__ ec) {
    int i = blockIdx.x, h = blockIdx.y;
    int tid = threadIdx.x, lane = tid & 31, wid = tid >> 5;
    int j = tid;
    __shared__ float s_r[12];
    __shared__ float s_feat[12 * 16];
    __shared__ float s_c[12 * 3];
    __shared__ float s_b;

    float sc = g_scores[(h * N_E + i) * N_E + j];
    float m = wmax(sc);
    if (lane == 0) s_r[wid] = m;
    __syncthreads();
    if (tid == 0) {
        float mm = s_r[0];
        for (int w = 1; w < 12; w++) mm = fmaxf(mm, s_r[w]);
        s_b = mm;
    }
    __syncthreads();
    float e = __expf(sc - s_b);
    float su = wsum(e);
    if (lane == 0) s_r[wid] = su;
    __syncthreads();
    if (tid == 0) {
        float ss = 0.f;
        for (int w = 0; w < 12; w++) ss += s_r[w];
        s_b = ss;
    }
    __syncthreads();
    float attn = __fdividef(e, s_b);

    float part[16];
    const float* vrow = g_v + j * HIDN + h * DHD;
#pragma unroll
    for (int d = 0; d < 16; d++) part[d] = attn * vrow[d];
#pragma unroll
    for (int d = 0; d < 16; d++) part[d] = wsum(part[d]);
    if (lane == 0) {
#pragma unroll
        for (int d = 0; d < 16; d++) s_feat[wid * 16 + d] = part[d];
    }

    float ga = g_gate[i * NHD + h] * attn;
    float cv[3];
    cv[0] = ga * (ec[i * 3 + 0] - ec[j * 3 + 0]);
    cv[1] = ga * (ec[i * 3 + 1] - ec[j * 3 + 1]);
    cv[2] = ga * (ec[i * 3 + 2] - ec[j * 3 + 2]);
#pragma unroll
    for (int d = 0; d < 3; d++) {
        float v = wsum(cv[d]);
        if (lane == 0) s_c[wid * 3 + d] = v;
    }
    __syncthreads();
    if (tid < 16) {
        float a = 0.f;
        for (int w = 0; w < 12; w++) a += s_feat[w * 16 + tid];
        g_upd[i * HIDN + h * DHD + tid] = a;
    }
    if (tid >= 32 && tid < 35) {
        int d = tid - 32;
        float a = 0.f;
        for (int w = 0; w < 12; w++) a += s_c[w * 3 + d];
        g_cpart[(i * NHD + h) * 3 + d] = a;
    }
}

// ---------------- kernel 6: output proj + layernorm + coords ----------------
__global__ void k_out(const float* __restrict__ ef, const float* __restrict__ wo,
                      const float* __restrict__ bo, const float* __restrict__ lng,
                      const float* __restrict__ lnb, const float* __restrict__ ec,
                      float* __restrict__ out) {
    int i = blockIdx.x, t = threadIdx.x, lane = t & 31, wid = t >> 5;
    __shared__ float s_u[HIDN];
    __shared__ float s_r[4];
    __shared__ float s_b;
    s_u[t] = g_upd[i * HIDN + t];
    __syncthreads();
    float acc = ef[i * HIDN + t] + bo[t];
#pragma unroll 4
    for (int c = 0; c < HIDN; c++) acc += s_u[c] * wo[c * HIDN + t];
    float m = wsum(acc);
    if (lane == 0) s_r[wid] = m;
    __syncthreads();
    if (t == 0) s_b = (s_r[0] + s_r[1] + s_r[2] + s_r[3]) * (1.0f / 128.0f);
    __syncthreads();
    float mu = s_b;
    float d = acc - mu;
    float v = wsum(d * d);
    __syncthreads();
    if (lane == 0) s_r[wid] = v;
    __syncthreads();
    if (t == 0) s_b = (s_r[0] + s_r[1] + s_r[2] + s_r[3]) * (1.0f / 128.0f);
    __syncthreads();
    out[i * HIDN + t] = d * rsqrtf(s_b + 1e-5f) * lng[t] + lnb[t];
    if (t < 3) {
        float a = 0.f;
#pragma unroll
        for (int h = 0; h < NHD; h++) a += g_cpart[(i * NHD + h) * 3 + t];
        out[N_E * HIDN + i * 3 + t] = ec[i * 3 + t] + a * 0.125f;
    }
}

// ---------------- launch ----------------
extern "C" void kernel_launch(void* const* d_in, const int* in_sizes, int n_in,
                              void* d_out, int out_size) {
    const float* ef = (const float*)d_in[0];
    const float* ec = (const float*)d_in[1];
    const float* mask = (const float*)d_in[2];
    const float* wq = (const float*)d_in[3];
    const float* wk = (const float*)d_in[4];
    const float* wv = (const float*)d_in[5];
    const float* rc = (const float*)d_in[6];
    const float* rw = (const float*)d_in[7];
    const float* aw1 = (const float*)d_in[8];
    const float* ab1 = (const float*)d_in[9];
    const float* aw2 = (const float*)d_in[10];
    const float* ab2 = (const float*)d_in[11];
    const float* aw3 = (const float*)d_in[12];
    const float* ab3 = (const float*)d_in[13];
    const float* gw1 = (const float*)d_in[14];
    const float* gb1 = (const float*)d_in[15];
    const float* gw2 = (const float*)d_in[16];
    const float* gb2 = (const float*)d_in[17];
    const float* wo = (const float*)d_in[18];
    const float* bo = (const float*)d_in[19];
    const float* lng = (const float*)d_in[20];
    const float* lnb = (const float*)d_in[21];
    float* out = (float*)d_out;

    // order chosen so the ncu capture slot lands on k_pair
    k_qkv<<<N_E, 128>>>(ef, wq, wk, wv);
    k_qckc<<<dim3(N_E, NHD), 128>>>(aw1);
    k_w2t<<<64, 256>>>(aw2);
    k_w1rb<<<64, 256>>>(aw1, ab1);

    cudaFuncSetAttribute(k_pair, cudaFuncAttributeMaxDynamicSharedMemorySize, K4_SMEM_BYTES);
    k_pair<<<NBLK, 256, K4_SMEM_BYTES>>>(ec, rc, rw, ab2, aw3, ab3, mask);

    k_gate<<<dim3(N_E, NHD), 128>>>(gw1, gb1, gw2, gb2);
    k_soft<<<dim3(N_E, NHD), N_E>>>(ec);
    k_out<<<N_E, 128>>>(ef, wo, bo, lng, lnb, ec, out);
}

// round 8
// speedup vs baseline: 3.5786x; 1.0104x over previous
#include <cuda_runtime.h>
#include <cuda_bf16.h>
#include <cstdint>

#define N_E 384
#define HIDN 128
#define NHD 8
#define DHD 16
#define PAIRS 16
#define NJB (N_E / PAIRS)     // 24
#define NTILES (N_E * NJB)    // 9216
#define NBLK 148

typedef unsigned long long ull;

// ---------------- scratch ----------------
__device__ float g_q[N_E * HIDN];
__device__ float g_k[N_E * HIDN];
__device__ float g_v[N_E * HIDN];
__device__ float g_qcT[N_E * HIDN * NHD];  // [i][c][h]
__device__ float g_kcT[N_E * HIDN * NHD];  // [j][c][h]
__device__ float g_gate[N_E * NHD];
__device__ float g_scores[NHD * N_E * N_E];
__device__ float g_upd[N_E * HIDN];
__device__ float g_cpart[N_E * NHD * 3];
__device__ __nv_bfloat16 g_w2t_hi[HIDN * HIDN];  // [cout][cin]
__device__ __nv_bfloat16 g_w2t_lo[HIDN * HIDN];
__device__ __nv_bfloat16 g_w1b_hi[HIDN * HIDN];  // [c][k] k: 0..64 rbf/dot, 65 bias
__device__ __nv_bfloat16 g_w1b_lo[HIDN * HIDN];

// ---------------- helpers ----------------
__device__ __forceinline__ float silu_f(float x) {
    return __fdividef(x, 1.0f + __expf(-x));
}
__device__ __forceinline__ float silu_t(float x) {  // tanh-based, 1 MUFU
    float hx = 0.5f * x, t;
    asm("tanh.approx.f32 %0, %1;" : "=f"(t) : "f"(hx));
    return fmaf(hx, t, hx);
}
__device__ __forceinline__ float wsum(float v) {
#pragma unroll
    for (int o = 16; o; o >>= 1) v += __shfl_xor_sync(0xffffffffu, v, o);
    return v;
}
__device__ __forceinline__ float wmax(float v) {
#pragma unroll
    for (int o = 16; o; o >>= 1) v = fmaxf(v, __shfl_xor_sync(0xffffffffu, v, o));
    return v;
}
__device__ __forceinline__ uint32_t smem_u32(const void* p) {
    uint32_t a;
    asm("{ .reg .u64 t; cvta.to.shared.u64 t, %1; cvt.u32.u64 %0, t; }" : "=r"(a) : "l"(p));
    return a;
}
__device__ __forceinline__ void mma16816(float* c, const uint32_t* a, const uint32_t* b) {
    asm volatile(
        "mma.sync.aligned.m16n8k16.row.col.f32.bf16.bf16.f32 "
        "{%0,%1,%2,%3}, {%4,%5,%6,%7}, {%8,%9}, {%0,%1,%2,%3};"
        : "+f"(c[0]), "+f"(c[1]), "+f"(c[2]), "+f"(c[3])
        : "r"(a[0]), "r"(a[1]), "r"(a[2]), "r"(a[3]), "r"(b[0]), "r"(b[1]));
}
__device__ __forceinline__ void ldsm4(uint32_t* r, uint32_t addr) {
    asm volatile("ldmatrix.sync.aligned.m8n8.x4.shared.b16 {%0,%1,%2,%3}, [%4];"
                 : "=r"(r[0]), "=r"(r[1]), "=r"(r[2]), "=r"(r[3]) : "r"(addr));
}
__device__ __forceinline__ uint32_t swz(int m, int cbyte) {
    return (uint32_t)(m * 256 + (cbyte ^ ((m & 7) << 4)));
}
__device__ __forceinline__ uint32_t pack_bf16x2(float lo, float hi) {
    uint32_t r;
    asm("cvt.rn.bf16x2.f32 %0, %1, %2;" : "=r"(r) : "f"(hi), "f"(lo));
    return r;
}

// ---------------- kernel 1: q,k,v projections ----------------
__global__ void k_qkv(const float* __restrict__ ef, const float* __restrict__ wq,
                      const float* __restrict__ wk, const float* __restrict__ wv) {
    int i = blockIdx.x, t = threadIdx.x;
    __shared__ float s_e[HIDN];
    s_e[t] = ef[i * HIDN + t];
    __syncthreads();
    float aq = 0.f, ak = 0.f, av = 0.f;
#pragma unroll 4
    for (int c = 0; c < HIDN; c++) {
        float e = s_e[c];
        aq += e * wq[c * HIDN + t];
        ak += e * wk[c * HIDN + t];
        av += e * wv[c * HIDN + t];
    }
    g_q[i * HIDN + t] = aq;
    g_k[i * HIDN + t] = ak;
    g_v[i * HIDN + t] = av;
}

// ---------------- kernel 2: qc/kc (transposed [edge][c][h]) ----------------
__global__ void k_qckc(const float* __restrict__ aw1) {
    int i = blockIdx.x, h = blockIdx.y, t = threadIdx.x;
    const float* qr = g_q + i * HIDN + h * DHD;
    const float* kr = g_k + i * HIDN + h * DHD;
    float aq = 0.f, ak = 0.f;
#pragma unroll
    for (int d = 0; d < DHD; d++) {
        aq += qr[d] * aw1[d * HIDN + t];
        ak += kr[d] * aw1[(DHD + d) * HIDN + t];
    }
    g_qcT[(i * HIDN + t) * NHD + h] = aq;
    g_kcT[(i * HIDN + t) * NHD + h] = ak;
}

// ---------------- kernel 3: gates ----------------
__global__ void k_gate(const float* __restrict__ gw1, const float* __restrict__ gb1,
                       const float* __restrict__ gw2, const float* __restrict__ gb2) {
    int i = blockIdx.x, h = blockIdx.y, t = threadIdx.x;
    int lane = t & 31, wid = t >> 5;
    const float* vr = g_v + i * HIDN + h * DHD;
    float acc = gb1[t];
#pragma unroll
    for (int d = 0; d < DHD; d++) acc += vr[d] * gw1[d * HIDN + t];
    float p = silu_f(acc) * gw2[t];
    p = wsum(p);
    __shared__ float sr[4];
    if (lane == 0) sr[wid] = p;
    __syncthreads();
    if (t == 0) {
        float s = sr[0] + sr[1] + sr[2] + sr[3] + gb2[0];
        g_gate[i * NHD + h] = __fdividef(1.0f, 1.0f + __expf(-s));
    }
}

// ---------------- kernel 3b: split w2^T into bf16 hi/lo ----------------
__global__ void k_w2t(const float* __restrict__ aw2) {
    int idx = blockIdx.x * 256 + threadIdx.x;  // 16384
    int cout = idx >> 7, cin = idx & 127;
    float w = aw2[cin * HIDN + cout];
    __nv_bfloat16 hi = __float2bfloat16_rn(w);
    float lo = w - __bfloat162float(hi);
    g_w2t_hi[idx] = hi;
    g_w2t_lo[idx] = __float2bfloat16_rn(lo);
}

// ---------------- kernel 3c: w1 geometric block as B-matrix [c][k] hi/lo ----------------
__global__ void k_w1rb(const float* __restrict__ aw1, const float* __restrict__ ab1) {
    int idx = blockIdx.x * 256 + threadIdx.x;  // 16384
    int c = idx >> 7, k = idx & 127;
    float w = 0.f;
    if (k < 65) w = aw1[(32 + k) * HIDN + c];
    else if (k == 65) w = ab1[c];
    __nv_bfloat16 hi = __float2bfloat16_rn(w);
    float lo = w - __bfloat162float(hi);
    g_w1b_hi[idx] = hi;
    g_w1b_lo[idx] = __float2bfloat16_rn(lo);
}

// ---------------- kernel 4: persistent pair-MLP, all GEMMs on HMMA, 512 thr ----------------
#define A_HI_OFF 0          // 32768 [128 m][256B]
#define A_LO_OFF 32768
#define B_HI_OFF 65536      // 32768 w2^T
#define B_LO_OFF 98304
#define W1B_HI_OFF 131072   // 32768 [c][256B]
#define W1B_LO_OFF 163840
#define RBF_HI_OFF 196608   // 4096 [16 p][256B]
#define RBF_LO_OFF 200704
#define BASE_OFF 204800     // 8192 f32 [16 p][128 c]
#define QCT_OFF 212992      // 4096 f32 [c][h]
#define W3T_OFF 217088      // 4096 f32 [h][c]
#define AB3_OFF 221184      // 32
#define RC_OFF 221216       // 256
#define RW_OFF 221472       // 256
#define SPART_OFF 221728    // 512
#define K4_SMEM_BYTES 222240

__global__ void __launch_bounds__(512, 1)
k_pair(const float* __restrict__ ec, const float* __restrict__ rc,
       const float* __restrict__ rw, const float* __restrict__ ab2,
       const float* __restrict__ aw3, const float* __restrict__ ab3,
       const float* __restrict__ mask) {
    extern __shared__ char sm[];
    const uint32_t sb = smem_u32(sm);
    float* s_base = (float*)(sm + BASE_OFF);
    float* s_qcT = (float*)(sm + QCT_OFF);
    float* s_w3T = (float*)(sm + W3T_OFF);
    float* s_ab3 = (float*)(sm + AB3_OFF);
    float* s_rc = (float*)(sm + RC_OFF);
    float* s_rw = (float*)(sm + RW_OFF);
    float* s_part = (float*)(sm + SPART_OFF);

    int tid = threadIdx.x, lane = tid & 31, warp = tid >> 5;
    int gid = lane >> 2, tid4 = lane & 3;
    int wm = warp >> 2, wn = warp & 3;   // main MMA: M-split 4 x N-split 4
    int cpi = tid & 63, pg2 = tid >> 6;  // silu stage: c2 = 2*cpi, pairs pg2*2..+1
    int c2 = cpi * 2;

    // ---- one-time init ----
    for (int idx = tid; idx < 1024; idx += 512) {
        int h = idx >> 7, c = idx & 127;
        s_w3T[idx] = aw3[c * NHD + h];
    }
    if (tid < 8) s_ab3[tid] = ab3[tid];
    if (tid < 64) {
        s_rc[tid] = rc[tid];
        s_rw[tid] = rw[tid];
    }
    for (int idx = tid; idx < 2048; idx += 512) {
        int n = idx >> 4, k0 = (idx & 15) * 8;
        uint32_t off = swz(n, k0 * 2);
        *(uint4*)(sm + B_HI_OFF + off) = *(const uint4*)(g_w2t_hi + n * HIDN + k0);
        *(uint4*)(sm + B_LO_OFF + off) = *(const uint4*)(g_w2t_lo + n * HIDN + k0);
        *(uint4*)(sm + W1B_HI_OFF + off) = *(const uint4*)(g_w1b_hi + n * HIDN + k0);
        *(uint4*)(sm + W1B_LO_OFF + off) = *(const uint4*)(g_w1b_lo + n * HIDN + k0);
    }
    for (int idx = tid; idx < 1024; idx += 512) {
        ((uint32_t*)(sm + RBF_HI_OFF))[idx] = 0;
        ((uint32_t*)(sm + RBF_LO_OFF))[idx] = 0;
    }
    __syncthreads();
    if (tid < 16) {
        *(uint16_t*)(sm + RBF_HI_OFF + swz(tid, 130)) = 0x3F80;  // bf16(1.0)
    }
    float b2r[8];
#pragma unroll
    for (int nb = 0; nb < 4; nb++) {
        int c0 = wn * 32 + nb * 8 + tid4 * 2;
        b2r[nb * 2] = ab2[c0];
        b2r[nb * 2 + 1] = ab2[c0 + 1];
    }
    __syncthreads();

    // ldmatrix lane addressing
    int a_row = lane & 15;
    int a_kh = (lane >> 4) & 1;
    int b_row_main = wn * 32 + ((lane >> 4) & 1) * 8 + (lane & 7);
    int b_row_base = warp * 16 + ((lane >> 4) & 1) * 8 + (lane & 7);  // warps 0-7 only
    int b_kh = (lane >> 3) & 1;

    for (int tile = blockIdx.x; tile < NTILES; tile += NBLK) {
        int i = tile / NJB;
        int j0 = (tile % NJB) * PAIRS;

        // ---- phase 1: rbf + dot; qcT; zero s_part ----
        if (tid < 128) s_part[tid] = 0.f;
        *(float2*)(&s_qcT[tid * 2]) = *(const float2*)(&g_qcT[i * 1024 + tid * 2]);
        float ci0 = ec[i * 3], ci1 = ec[i * 3 + 1], ci2 = ec[i * 3 + 2];
        {
            int p = tid & 15, rq = tid >> 4;  // rq 0..31 -> r = 2rq, 2rq+1
            int j = j0 + p;
            float cj0 = ec[j * 3], cj1 = ec[j * 3 + 1], cj2 = ec[j * 3 + 2];
            float dx = ci0 - cj0, dy = ci1 - cj1, dz = ci2 - cj2;
            float dist = sqrtf(dx * dx + dy * dy + dz * dz) + 1e-8f;
            dist = fminf(fmaxf(dist, 1e-8f), 1e8f);
            int r0 = rq * 2, r1 = r0 + 1;
            float d0 = dist - s_rc[r0], d1 = dist - s_rc[r1];
            float v0 = (dist <= 10.0f) ? __expf(-s_rw[r0] * d0 * d0) : 0.0f;
            float v1 = (dist <= 10.0f) ? __expf(-s_rw[r1] * d1 * d1) : 0.0f;
            uint32_t hp = pack_bf16x2(v0, v1);
            float e0 = v0 - __uint_as_float(hp << 16);
            float e1 = v1 - __uint_as_float(hp & 0xFFFF0000u);
            uint32_t lp = pack_bf16x2(e0, e1);
            uint32_t off = swz(p, rq * 4);
            *(uint32_t*)(sm + RBF_HI_OFF + off) = hp;
            *(uint32_t*)(sm + RBF_LO_OFF + off) = lp;
        }
        if (tid < 16) {
            int j = j0 + tid;
            float cj0 = ec[j * 3], cj1 = ec[j * 3 + 1], cj2 = ec[j * 3 + 2];
            float dot = ci0 * cj0 + ci1 * cj1 + ci2 * cj2;
            dot = fminf(fmaxf(dot, -1e8f), 1e8f);
            __nv_bfloat16 dh = __float2bfloat16_rn(dot);
            __nv_bfloat16 dl = __float2bfloat16_rn(dot - __bfloat162float(dh));
            uint32_t off = swz(tid, 128);
            *(uint16_t*)(sm + RBF_HI_OFF + off) = *(uint16_t*)&dh;
            *(uint16_t*)(sm + RBF_LO_OFF + off) = *(uint16_t*)&dl;
        }

        // kc prefetch for phase 3 (latency overlapped with phase 2 GEMM)
        float kcA[16], kcB[16];
        {
            const float* kcp0 = g_kcT + ((j0 + pg2 * 2) * HIDN + c2) * 8;
            const float* kcp1 = g_kcT + ((j0 + pg2 * 2 + 1) * HIDN + c2) * 8;
            *(float4*)(kcA) = *(const float4*)(kcp0);
            *(float4*)(kcA + 4) = *(const float4*)(kcp0 + 4);
            *(float4*)(kcA + 8) = *(const float4*)(kcp0 + 8);
            *(float4*)(kcA + 12) = *(const float4*)(kcp0 + 12);
            *(float4*)(kcB) = *(const float4*)(kcp1);
            *(float4*)(kcB + 4) = *(const float4*)(kcp1 + 4);
            *(float4*)(kcB + 8) = *(const float4*)(kcp1 + 8);
            *(float4*)(kcB + 12) = *(const float4*)(kcp1 + 12);
        }
        __syncthreads();

        // ---- phase 2: base GEMM (16 x 128, K eff 66); warps 0-7 ----
        if (warp < 8) {
            float bacc[2][4];
#pragma unroll
            for (int nb = 0; nb < 2; nb++)
#pragma unroll
                for (int q = 0; q < 4; q++) bacc[nb][q] = 0.f;
#pragma unroll
            for (int kb = 0; kb < 5; kb++) {
                uint32_t rhi[4], rlo[4];
                ldsm4(rhi, sb + RBF_HI_OFF + swz(a_row, kb * 32 + a_kh * 16));
                ldsm4(rlo, sb + RBF_LO_OFF + swz(a_row, kb * 32 + a_kh * 16));
                uint32_t boff = swz(b_row_base, kb * 32 + b_kh * 16);
                uint32_t rr[4];
                uint32_t wh[2][2], wl[2][2];
                ldsm4(rr, sb + W1B_HI_OFF + boff);
                wh[0][0] = rr[0]; wh[0][1] = rr[1]; wh[1][0] = rr[2]; wh[1][1] = rr[3];
                ldsm4(rr, sb + W1B_LO_OFF + boff);
                wl[0][0] = rr[0]; wl[0][1] = rr[1]; wl[1][0] = rr[2]; wl[1][1] = rr[3];
#pragma unroll
                for (int nb = 0; nb < 2; nb++) {
                    mma16816(bacc[nb], rhi, wh[nb]);
                    mma16816(bacc[nb], rlo, wh[nb]);
                    mma16816(bacc[nb], rhi, wl[nb]);
                }
            }
#pragma unroll
            for (int nb = 0; nb < 2; nb++) {
                int c0 = warp * 16 + nb * 8 + tid4 * 2;
                float2 v0 = {bacc[nb][0], bacc[nb][1]};
                float2 v1 = {bacc[nb][2], bacc[nb][3]};
                *(float2*)(&s_base[gid * 128 + c0]) = v0;
                *(float2*)(&s_base[(gid + 8) * 128 + c0]) = v1;
            }
        }
        __syncthreads();

        // ---- phase 3: x1 = silu(base + qc + kc) -> A_hi/A_lo ----
        {
            float qv0[8], qv1[8];
            *(float4*)(qv0) = *(const float4*)(&s_qcT[c2 * 8]);
            *(float4*)(qv0 + 4) = *(const float4*)(&s_qcT[c2 * 8 + 4]);
            *(float4*)(qv1) = *(const float4*)(&s_qcT[c2 * 8 + 8]);
            *(float4*)(qv1 + 4) = *(const float4*)(&s_qcT[c2 * 8 + 12]);
#pragma unroll
            for (int pp = 0; pp < 2; pp++) {
                int p = pg2 * 2 + pp;
                float2 bs = *(const float2*)(&s_base[p * 128 + c2]);
                const float* kc = pp ? kcB : kcA;
#pragma unroll
                for (int h = 0; h < NHD; h++) {
                    float x0 = silu_t(bs.x + qv0[h] + kc[h]);
                    float x1 = silu_t(bs.y + qv1[h] + kc[h + 8]);
                    uint32_t hp = pack_bf16x2(x0, x1);
                    float r0 = x0 - __uint_as_float(hp << 16);
                    float r1 = x1 - __uint_as_float(hp & 0xFFFF0000u);
                    uint32_t lp = pack_bf16x2(r0, r1);
                    int m = h * PAIRS + p;
                    uint32_t off = swz(m, c2 * 2);
                    *(uint32_t*)(sm + A_HI_OFF + off) = hp;
                    *(uint32_t*)(sm + A_LO_OFF + off) = lp;
                }
            }
        }
        __syncthreads();

        // ---- phase 4: main GEMM D = Ahi*Bhi + Alo*Bhi + Ahi*Blo ----
        float acc[2][4][4];
#pragma unroll
        for (int mb = 0; mb < 2; mb++)
#pragma unroll
            for (int nb = 0; nb < 4; nb++)
#pragma unroll
                for (int q = 0; q < 4; q++) acc[mb][nb][q] = 0.f;

#pragma unroll
        for (int kb = 0; kb < 8; kb++) {
            uint32_t bh[4][2], bl[4][2];
#pragma unroll
            for (int nb2 = 0; nb2 < 2; nb2++) {
                uint32_t boff = swz(b_row_main + nb2 * 16, kb * 32 + b_kh * 16);
                uint32_t rr[4];
                ldsm4(rr, sb + B_HI_OFF + boff);
                bh[nb2 * 2][0] = rr[0]; bh[nb2 * 2][1] = rr[1];
                bh[nb2 * 2 + 1][0] = rr[2]; bh[nb2 * 2 + 1][1] = rr[3];
                ldsm4(rr, sb + B_LO_OFF + boff);
                bl[nb2 * 2][0] = rr[0]; bl[nb2 * 2][1] = rr[1];
                bl[nb2 * 2 + 1][0] = rr[2]; bl[nb2 * 2 + 1][1] = rr[3];
            }
#pragma unroll
            for (int mb = 0; mb < 2; mb++) {
                uint32_t aoff = swz(wm * 32 + mb * 16 + a_row, kb * 32 + a_kh * 16);
                uint32_t ahi[4], alo[4];
                ldsm4(ahi, sb + A_HI_OFF + aoff);
                ldsm4(alo, sb + A_LO_OFF + aoff);
#pragma unroll
                for (int nb = 0; nb < 4; nb++) {
                    mma16816(acc[mb][nb], ahi, bh[nb]);
                    mma16816(acc[mb][nb], alo, bh[nb]);
                    mma16816(acc[mb][nb], ahi, bl[nb]);
                }
            }
        }

        // ---- phase 5: epilogue silu(D+b2).w3 -> s_part ----
#pragma unroll
        for (int mb = 0; mb < 2; mb++) {
            int h = wm * 2 + mb;
            float p0 = 0.f, p1 = 0.f;
#pragma unroll
            for (int nb = 0; nb < 4; nb++) {
                int c0 = wn * 32 + nb * 8 + tid4 * 2;
                float2 w3v = *(const float2*)(&s_w3T[h * 128 + c0]);
                p0 += silu_t(acc[mb][nb][0] + b2r[nb * 2]) * w3v.x +
                      silu_t(acc[mb][nb][1] + b2r[nb * 2 + 1]) * w3v.y;
                p1 += silu_t(acc[mb][nb][2] + b2r[nb * 2]) * w3v.x +
                      silu_t(acc[mb][nb][3] + b2r[nb * 2 + 1]) * w3v.y;
            }
            p0 += __shfl_xor_sync(0xffffffffu, p0, 1);
            p0 += __shfl_xor_sync(0xffffffffu, p0, 2);
            p1 += __shfl_xor_sync(0xffffffffu, p1, 1);
            p1 += __shfl_xor_sync(0xffffffffu, p1, 2);
            if (tid4 == 0) {
                int m = wm * 32 + mb * 16 + gid;
                atomicAdd(&s_part[m], p0);
                atomicAdd(&s_part[m + 8], p1);
            }
        }
        __syncthreads();

        if (tid < 128) {
            int h = tid >> 4, p = tid & 15;
            int j = j0 + p;
            float s = s_part[tid] + s_ab3[h] + mask[i * N_E + j];
            s = fminf(fmaxf(s, -1e9f), 1e9f);
            g_scores[(h * N_E + i) * N_E + j] = s;
        }
        __syncthreads();
    }
}

// ---------------- kernel 5: softmax + feats + coord partials ----------------
__global__ void k_soft(const float* __restrict__ ec) {
    int i = blockIdx.x, h = blockIdx.y;
    int tid = threadIdx.x, lane = tid & 31, wid = tid >> 5;
    int j = tid;
    __shared__ float s_r[12];
    __shared__ float s_feat[12 * 16];
    __shared__ float s_c[12 * 3];
    __shared__ float s_b;

    float sc = g_scores[(h * N_E + i) * N_E + j];
    float m = wmax(sc);
    if (lane == 0) s_r[wid] = m;
    __syncthreads();
    if (tid == 0) {
        float mm = s_r[0];
        for (int w = 1; w < 12; w++) mm = fmaxf(mm, s_r[w]);
        s_b = mm;
    }
    __syncthreads();
    float e = __expf(sc - s_b);
    float su = wsum(e);
    if (lane == 0) s_r[wid] = su;
    __syncthreads();
    if (tid == 0) {
        float ss = 0.f;
        for (int w = 0; w < 12; w++) ss += s_r[w];
        s_b = ss;
    }
    __syncthreads();
    float attn = __fdividef(e, s_b);

    float part[16];
    const float* vrow = g_v + j * HIDN + h * DHD;
#pragma unroll
    for (int d = 0; d < 16; d++) part[d] = attn * vrow[d];
#pragma unroll
    for (int d = 0; d < 16; d++) part[d] = wsum(part[d]);
    if (lane == 0) {
#pragma unroll
        for (int d = 0; d < 16; d++) s_feat[wid * 16 + d] = part[d];
    }

    float ga = g_gate[i * NHD + h] * attn;
    float cv[3];
    cv[0] = ga * (ec[i * 3 + 0] - ec[j * 3 + 0]);
    cv[1] = ga * (ec[i * 3 + 1] - ec[j * 3 + 1]);
    cv[2] = ga * (ec[i * 3 + 2] - ec[j * 3 + 2]);
#pragma unroll
    for (int d = 0; d < 3; d++) {
        float v = wsum(cv[d]);
        if (lane == 0) s_c[wid * 3 + d] = v;
    }
    __syncthreads();
    if (tid < 16) {
        float a = 0.f;
        for (int w = 0; w < 12; w++) a += s_feat[w * 16 + tid];
        g_upd[i * HIDN + h * DHD + tid] = a;
    }
    if (tid >= 32 && tid < 35) {
        int d = tid - 32;
        float a = 0.f;
        for (int w = 0; w < 12; w++) a += s_c[w * 3 + d];
        g_cpart[(i * NHD + h) * 3 + d] = a;
    }
}

// ---------------- kernel 6: output proj + layernorm + coords ----------------
__global__ void k_out(const float* __restrict__ ef, const float* __restrict__ wo,
                      const float* __restrict__ bo, const float* __restrict__ lng,
                      const float* __restrict__ lnb, const float* __restrict__ ec,
                      float* __restrict__ out) {
    int i = blockIdx.x, t = threadIdx.x, lane = t & 31, wid = t >> 5;
    __shared__ float s_u[HIDN];
    __shared__ float s_r[4];
    __shared__ float s_b;
    s_u[t] = g_upd[i * HIDN + t];
    __syncthreads();
    float acc = ef[i * HIDN + t] + bo[t];
#pragma unroll 4
    for (int c = 0; c < HIDN; c++) acc += s_u[c] * wo[c * HIDN + t];
    float m = wsum(acc);
    if (lane == 0) s_r[wid] = m;
    __syncthreads();
    if (t == 0) s_b = (s_r[0] + s_r[1] + s_r[2] + s_r[3]) * (1.0f / 128.0f);
    __syncthreads();
    float mu = s_b;
    float d = acc - mu;
    float v = wsum(d * d);
    __syncthreads();
    if (lane == 0) s_r[wid] = v;
    __syncthreads();
    if (t == 0) s_b = (s_r[0] + s_r[1] + s_r[2] + s_r[3]) * (1.0f / 128.0f);
    __syncthreads();
    out[i * HIDN + t] = d * rsqrtf(s_b + 1e-5f) * lng[t] + lnb[t];
    if (t < 3) {
        float a = 0.f;
#pragma unroll
        for (int h = 0; h < NHD; h++) a += g_cpart[(i * NHD + h) * 3 + t];
        out[N_E * HIDN + i * 3 + t] = ec[i * 3 + t] + a * 0.125f;
    }
}

// ---------------- launch ----------------
extern "C" void kernel_launch(void* const* d_in, const int* in_sizes, int n_in,
                              void* d_out, int out_size) {
    const float* ef = (const float*)d_in[0];
    const float* ec = (const float*)d_in[1];
    const float* mask = (const float*)d_in[2];
    const float* wq = (const float*)d_in[3];
    const float* wk = (const float*)d_in[4];
    const float* wv = (const float*)d_in[5];
    const float* rc = (const float*)d_in[6];
    const float* rw = (const float*)d_in[7];
    const float* aw1 = (const float*)d_in[8];
    const float* ab1 = (const float*)d_in[9];
    const float* aw2 = (const float*)d_in[10];
    const float* ab2 = (const float*)d_in[11];
    const float* aw3 = (const float*)d_in[12];
    const float* ab3 = (const float*)d_in[13];
    const float* gw1 = (const float*)d_in[14];
    const float* gb1 = (const float*)d_in[15];
    const float* gw2 = (const float*)d_in[16];
    const float* gb2 = (const float*)d_in[17];
    const float* wo = (const float*)d_in[18];
    const float* bo = (const float*)d_in[19];
    const float* lng = (const float*)d_in[20];
    const float* lnb = (const float*)d_in[21];
    float* out = (float*)d_out;

    k_qkv<<<N_E, 128>>>(ef, wq, wk, wv);
    k_qckc<<<dim3(N_E, NHD), 128>>>(aw1);
    k_w2t<<<64, 256>>>(aw2);
    k_w1rb<<<64, 256>>>(aw1, ab1);

    cudaFuncSetAttribute(k_pair, cudaFuncAttributeMaxDynamicSharedMemorySize, K4_SMEM_BYTES);
    k_pair<<<NBLK, 512, K4_SMEM_BYTES>>>(ec, rc, rw, ab2, aw3, ab3, mask);

    k_gate<<<dim3(N_E, NHD), 128>>>(gw1, gb1, gw2, gb2);
    k_soft<<<dim3(N_E, NHD), N_E>>>(ec);
    k_out<<<N_E, 128>>>(ef, wo, bo, lng, lnb, ec, out);
}

// round 10
// speedup vs baseline: 4.0648x; 1.1359x over previous
#include <cuda_runtime.h>
#include <cuda_bf16.h>
#include <cuda_fp16.h>
#include <cstdint>

#define N_E 384
#define HIDN 128
#define NHD 8
#define DHD 16
#define PAIRS 16
#define NJB (N_E / PAIRS)     // 24
#define NTILES (N_E * NJB)    // 9216
#define NBLK 148

typedef unsigned long long ull;

// ---------------- scratch ----------------
__device__ float g_q[N_E * HIDN];
__device__ float g_k[N_E * HIDN];
__device__ float g_v[N_E * HIDN];
__device__ float g_qcT[N_E * HIDN * NHD];  // [i][c][h]
__device__ float g_kcT[N_E * HIDN * NHD];  // [j][c][h]
__device__ float g_gate[N_E * NHD];
__device__ float g_scores[NHD * N_E * N_E];
__device__ float g_upd[N_E * HIDN];
__device__ float g_cpart[N_E * NHD * 3];
__device__ __half g_w2t_h[HIDN * HIDN];   // [cout][cin] fp16
__device__ __half g_w1b_h[HIDN * HIDN];   // [c][k] k: 0..64 rbf/dot, 65 bias

// ---------------- helpers ----------------
__device__ __forceinline__ float silu_f(float x) {
    return __fdividef(x, 1.0f + __expf(-x));
}
__device__ __forceinline__ float silu_t(float x) {  // tanh-based, 1 MUFU
    float hx = 0.5f * x, t;
    asm("tanh.approx.f32 %0, %1;" : "=f"(t) : "f"(hx));
    return fmaf(hx, t, hx);
}
__device__ __forceinline__ float wsum(float v) {
#pragma unroll
    for (int o = 16; o; o >>= 1) v += __shfl_xor_sync(0xffffffffu, v, o);
    return v;
}
__device__ __forceinline__ float wmax(float v) {
#pragma unroll
    for (int o = 16; o; o >>= 1) v = fmaxf(v, __shfl_xor_sync(0xffffffffu, v, o));
    return v;
}
__device__ __forceinline__ uint32_t smem_u32(const void* p) {
    uint32_t a;
    asm("{ .reg .u64 t; cvta.to.shared.u64 t, %1; cvt.u32.u64 %0, t; }" : "=r"(a) : "l"(p));
    return a;
}
// fp16 m16n8k16 HMMA, D += A*B
__device__ __forceinline__ void mma16816(float* c, const uint32_t* a, const uint32_t* b) {
    asm volatile(
        "mma.sync.aligned.m16n8k16.row.col.f32.f16.f16.f32 "
        "{%0,%1,%2,%3}, {%4,%5,%6,%7}, {%8,%9}, {%0,%1,%2,%3};"
        : "+f"(c[0]), "+f"(c[1]), "+f"(c[2]), "+f"(c[3])
        : "r"(a[0]), "r"(a[1]), "r"(a[2]), "r"(a[3]), "r"(b[0]), "r"(b[1]));
}
__device__ __forceinline__ void ldsm4(uint32_t* r, uint32_t addr) {
    asm volatile("ldmatrix.sync.aligned.m8n8.x4.shared.b16 {%0,%1,%2,%3}, [%4];"
                 : "=r"(r[0]), "=r"(r[1]), "=r"(r[2]), "=r"(r[3]) : "r"(addr));
}
__device__ __forceinline__ uint32_t swz(int m, int cbyte) {
    return (uint32_t)(m * 256 + (cbyte ^ ((m & 7) << 4)));
}

// ---------------- kernel 1: q,k,v projections ----------------
__global__ void k_qkv(const float* __restrict__ ef, const float* __restrict__ wq,
                      const float* __restrict__ wk, const float* __restrict__ wv) {
    int i = blockIdx.x, t = threadIdx.x;
    __shared__ float s_e[HIDN];
    s_e[t] = ef[i * HIDN + t];
    __syncthreads();
    float aq = 0.f, ak = 0.f, av = 0.f;
#pragma unroll 4
    for (int c = 0; c < HIDN; c++) {
        float e = s_e[c];
        aq += e * wq[c * HIDN + t];
        ak += e * wk[c * HIDN + t];
        av += e * wv[c * HIDN + t];
    }
    g_q[i * HIDN + t] = aq;
    g_k[i * HIDN + t] = ak;
    g_v[i * HIDN + t] = av;
}

// ---------------- kernel 2: qc/kc (transposed [edge][c][h]) ----------------
__global__ void k_qckc(const float* __restrict__ aw1) {
    int i = blockIdx.x, h = blockIdx.y, t = threadIdx.x;
    const float* qr = g_q + i * HIDN + h * DHD;
    const float* kr = g_k + i * HIDN + h * DHD;
    float aq = 0.f, ak = 0.f;
#pragma unroll
    for (int d = 0; d < DHD; d++) {
        aq += qr[d] * aw1[d * HIDN + t];
        ak += kr[d] * aw1[(DHD + d) * HIDN + t];
    }
    g_qcT[(i * HIDN + t) * NHD + h] = aq;
    g_kcT[(i * HIDN + t) * NHD + h] = ak;
}

// ---------------- kernel 3: gates ----------------
__global__ void k_gate(const float* __restrict__ gw1, const float* __restrict__ gb1,
                       const float* __restrict__ gw2, const float* __restrict__ gb2) {
    int i = blockIdx.x, h = blockIdx.y, t = threadIdx.x;
    int lane = t & 31, wid = t >> 5;
    const float* vr = g_v + i * HIDN + h * DHD;
    float acc = gb1[t];
#pragma unroll
    for (int d = 0; d < DHD; d++) acc += vr[d] * gw1[d * HIDN + t];
    float p = silu_f(acc) * gw2[t];
    p = wsum(p);
    __shared__ float sr[4];
    if (lane == 0) sr[wid] = p;
    __syncthreads();
    if (t == 0) {
        float s = sr[0] + sr[1] + sr[2] + sr[3] + gb2[0];
        g_gate[i * NHD + h] = __fdividef(1.0f, 1.0f + __expf(-s));
    }
}

// ---------------- kernel 3b: w2^T fp16 ----------------
__global__ void k_w2t(const float* __restrict__ aw2) {
    int idx = blockIdx.x * 256 + threadIdx.x;  // 16384
    int cout = idx >> 7, cin = idx & 127;
    g_w2t_h[idx] = __float2half_rn(aw2[cin * HIDN + cout]);
}

// ---------------- kernel 3c: w1 geometric block fp16 [c][k] ----------------
__global__ void k_w1rb(const float* __restrict__ aw1, const float* __restrict__ ab1) {
    int idx = blockIdx.x * 256 + threadIdx.x;  // 16384
    int c = idx >> 7, k = idx & 127;
    float w = 0.f;
    if (k < 65) w = aw1[(32 + k) * HIDN + c];
    else if (k == 65) w = ab1[c];
    g_w1b_h[idx] = __float2half_rn(w);
}

// ---------------- kernel 4: persistent pair-MLP, fp16 2-pass HMMA, 512 thr ----------------
#define A_HI_OFF 0          // 32768 [128 m][256B]
#define A_LO_OFF 32768      // 32768
#define B_H_OFF 65536       // 32768 w2^T fp16
#define W1B_H_OFF 98304     // 32768 [c][256B]
#define RBF_HI_OFF 131072   // 4096 [16 p][256B]
#define RBF_LO_OFF 135168   // 4096
#define BASE_OFF 139264     // 8192 f32 [16 p][128 c]
#define QCT_OFF 147456      // 4096 f32 [c][h]
#define W3T_OFF 151552      // 4096 f32 [h][c]
#define AB3_OFF 155648      // 32
#define RC_OFF 155680       // 256
#define RW_OFF 155936       // 256
#define SPART_OFF 156192    // 512
#define K4_SMEM_BYTES 156704

__global__ void __launch_bounds__(512, 1)
k_pair(const float* __restrict__ ec, const float* __restrict__ rc,
       const float* __restrict__ rw, const float* __restrict__ ab2,
       const float* __restrict__ aw3, const float* __restrict__ ab3,
       const float* __restrict__ mask) {
    extern __shared__ char sm[];
    const uint32_t sb = smem_u32(sm);
    float* s_base = (float*)(sm + BASE_OFF);
    float* s_qcT = (float*)(sm + QCT_OFF);
    float* s_w3T = (float*)(sm + W3T_OFF);
    float* s_ab3 = (float*)(sm + AB3_OFF);
    float* s_rc = (float*)(sm + RC_OFF);
    float* s_rw = (float*)(sm + RW_OFF);
    float* s_part = (float*)(sm + SPART_OFF);

    int tid = threadIdx.x, lane = tid & 31, warp = tid >> 5;
    int gid = lane >> 2, tid4 = lane & 3;
    int wm = warp >> 2, wn = warp & 3;   // main MMA: M-split 4 x N-split 4
    int cpi = tid & 63, pg2 = tid >> 6;  // silu stage: c2 = 2*cpi, pairs pg2*2..+1
    int c2 = cpi * 2;

    // ---- one-time init ----
    for (int idx = tid; idx < 1024; idx += 512) {
        int h = idx >> 7, c = idx & 127;
        s_w3T[idx] = aw3[c * NHD + h];
    }
    if (tid < 8) s_ab3[tid] = ab3[tid];
    if (tid < 64) {
        s_rc[tid] = rc[tid];
        s_rw[tid] = rw[tid];
    }
    for (int idx = tid; idx < 2048; idx += 512) {
        int n = idx >> 4, k0 = (idx & 15) * 8;
        uint32_t off = swz(n, k0 * 2);
        *(uint4*)(sm + B_H_OFF + off) = *(const uint4*)(g_w2t_h + n * HIDN + k0);
        *(uint4*)(sm + W1B_H_OFF + off) = *(const uint4*)(g_w1b_h + n * HIDN + k0);
    }
    for (int idx = tid; idx < 1024; idx += 512) {
        ((uint32_t*)(sm + RBF_HI_OFF))[idx] = 0;
        ((uint32_t*)(sm + RBF_LO_OFF))[idx] = 0;
    }
    __syncthreads();
    if (tid < 16) {
        *(uint16_t*)(sm + RBF_HI_OFF + swz(tid, 130)) = 0x3C00;  // fp16(1.0)
    }
    float b2r[8];
#pragma unroll
    for (int nb = 0; nb < 4; nb++) {
        int c0 = wn * 32 + nb * 8 + tid4 * 2;
        b2r[nb * 2] = ab2[c0];
        b2r[nb * 2 + 1] = ab2[c0 + 1];
    }
    __syncthreads();

    // ldmatrix lane addressing
    int a_row = lane & 15;
    int a_kh = (lane >> 4) & 1;
    int b_row_main = wn * 32 + ((lane >> 4) & 1) * 8 + (lane & 7);
    int b_row_base = warp * 16 + ((lane >> 4) & 1) * 8 + (lane & 7);  // warps 0-7 only
    int b_kh = (lane >> 3) & 1;

    for (int tile = blockIdx.x; tile < NTILES; tile += NBLK) {
        int i = tile / NJB;
        int j0 = (tile % NJB) * PAIRS;

        // ---- phase 1: rbf + dot; qcT; zero s_part ----
        if (tid < 128) s_part[tid] = 0.f;
        *(float2*)(&s_qcT[tid * 2]) = *(const float2*)(&g_qcT[i * 1024 + tid * 2]);
        float ci0 = ec[i * 3], ci1 = ec[i * 3 + 1], ci2 = ec[i * 3 + 2];
        {
            int p = tid & 15, rq = tid >> 4;  // rq 0..31 -> r = 2rq, 2rq+1
            int j = j0 + p;
            float cj0 = ec[j * 3], cj1 = ec[j * 3 + 1], cj2 = ec[j * 3 + 2];
            float dx = ci0 - cj0, dy = ci1 - cj1, dz = ci2 - cj2;
            float dist = sqrtf(dx * dx + dy * dy + dz * dz) + 1e-8f;
            dist = fminf(fmaxf(dist, 1e-8f), 1e8f);
            int r0 = rq * 2, r1 = r0 + 1;
            float d0 = dist - s_rc[r0], d1 = dist - s_rc[r1];
            float v0 = (dist <= 10.0f) ? __expf(-s_rw[r0] * d0 * d0) : 0.0f;
            float v1 = (dist <= 10.0f) ? __expf(-s_rw[r1] * d1 * d1) : 0.0f;
            __half2 hh = __floats2half2_rn(v0, v1);
            float e0 = v0 - __half2float(__low2half(hh));
            float e1 = v1 - __half2float(__high2half(hh));
            __half2 ll = __floats2half2_rn(e0, e1);
            uint32_t off = swz(p, rq * 4);
            *(uint32_t*)(sm + RBF_HI_OFF + off) = *(uint32_t*)&hh;
            *(uint32_t*)(sm + RBF_LO_OFF + off) = *(uint32_t*)&ll;
        }
        if (tid < 16) {
            int j = j0 + tid;
            float cj0 = ec[j * 3], cj1 = ec[j * 3 + 1], cj2 = ec[j * 3 + 2];
            float dot = ci0 * cj0 + ci1 * cj1 + ci2 * cj2;
            dot = fminf(fmaxf(dot, -1e8f), 1e8f);
            __half dh = __float2half_rn(dot);
            __half dl = __float2half_rn(dot - __half2float(dh));
            uint32_t off = swz(tid, 128);
            *(uint16_t*)(sm + RBF_HI_OFF + off) = *(uint16_t*)&dh;
            *(uint16_t*)(sm + RBF_LO_OFF + off) = *(uint16_t*)&dl;
        }

        // kc prefetch for phase 3 (latency overlapped with phase 2 GEMM)
        float kcA[16], kcB[16];
        {
            const float* kcp0 = g_kcT + ((j0 + pg2 * 2) * HIDN + c2) * 8;
            const float* kcp1 = g_kcT + ((j0 + pg2 * 2 + 1) * HIDN + c2) * 8;
            *(float4*)(kcA) = *(const float4*)(kcp0);
            *(float4*)(kcA + 4) = *(const float4*)(kcp0 + 4);
            *(float4*)(kcA + 8) = *(const float4*)(kcp0 + 8);
            *(float4*)(kcA + 12) = *(const float4*)(kcp0 + 12);
            *(float4*)(kcB) = *(const float4*)(kcp1);
            *(float4*)(kcB + 4) = *(const float4*)(kcp1 + 4);
            *(float4*)(kcB + 8) = *(const float4*)(kcp1 + 8);
            *(float4*)(kcB + 12) = *(const float4*)(kcp1 + 12);
        }
        __syncthreads();

        // ---- phase 2: base GEMM (16 x 128, K eff 66), 2-pass; warps 0-7 ----
        if (warp < 8) {
            float bacc[2][4];
#pragma unroll
            for (int nb = 0; nb < 2; nb++)
#pragma unroll
                for (int q = 0; q < 4; q++) bacc[nb][q] = 0.f;
#pragma unroll
            for (int kb = 0; kb < 5; kb++) {
                uint32_t rhi[4], rlo[4];
                ldsm4(rhi, sb + RBF_HI_OFF + swz(a_row, kb * 32 + a_kh * 16));
                ldsm4(rlo, sb + RBF_LO_OFF + swz(a_row, kb * 32 + a_kh * 16));
                uint32_t boff = swz(b_row_base, kb * 32 + b_kh * 16);
                uint32_t rr[4];
                uint32_t wh[2][2];
                ldsm4(rr, sb + W1B_H_OFF + boff);
                wh[0][0] = rr[0]; wh[0][1] = rr[1]; wh[1][0] = rr[2]; wh[1][1] = rr[3];
#pragma unroll
                for (int nb = 0; nb < 2; nb++) {
                    mma16816(bacc[nb], rhi, wh[nb]);
                    mma16816(bacc[nb], rlo, wh[nb]);
                }
            }
#pragma unroll
            for (int nb = 0; nb < 2; nb++) {
                int c0 = warp * 16 + nb * 8 + tid4 * 2;
                float2 v0 = {bacc[nb][0], bacc[nb][1]};
                float2 v1 = {bacc[nb][2], bacc[nb][3]};
                *(float2*)(&s_base[gid * 128 + c0]) = v0;
                *(float2*)(&s_base[(gid + 8) * 128 + c0]) = v1;
            }
        }
        __syncthreads();

        // ---- phase 3: x1 = silu(base + qc + kc) -> A_hi/A_lo (fp16 split) ----
        {
            float qv0[8], qv1[8];
            *(float4*)(qv0) = *(const float4*)(&s_qcT[c2 * 8]);
            *(float4*)(qv0 + 4) = *(const float4*)(&s_qcT[c2 * 8 + 4]);
            *(float4*)(qv1) = *(const float4*)(&s_qcT[c2 * 8 + 8]);
            *(float4*)(qv1 + 4) = *(const float4*)(&s_qcT[c2 * 8 + 12]);
#pragma unroll
            for (int pp = 0; pp < 2; pp++) {
                int p = pg2 * 2 + pp;
                float2 bs = *(const float2*)(&s_base[p * 128 + c2]);
                const float* kc = pp ? kcB : kcA;
#pragma unroll
                for (int h = 0; h < NHD; h++) {
                    float x0 = silu_t(bs.x + qv0[h] + kc[h]);
                    float x1 = silu_t(bs.y + qv1[h] + kc[h + 8]);
                    __half2 hh = __floats2half2_rn(x0, x1);
                    float r0 = x0 - __half2float(__low2half(hh));
                    float r1 = x1 - __half2float(__high2half(hh));
                    __half2 ll = __floats2half2_rn(r0, r1);
                    int m = h * PAIRS + p;
                    uint32_t off = swz(m, c2 * 2);
                    *(uint32_t*)(sm + A_HI_OFF + off) = *(uint32_t*)&hh;
                    *(uint32_t*)(sm + A_LO_OFF + off) = *(uint32_t*)&ll;
                }
            }
        }
        __syncthreads();

        // ---- phase 4: main GEMM D = (Ahi + Alo) * Bh (2-pass fp16) ----
        float acc[2][4][4];
#pragma unroll
        for (int mb = 0; mb < 2; mb++)
#pragma unroll
            for (int nb = 0; nb < 4; nb++)
#pragma unroll
                for (int q = 0; q < 4; q++) acc[mb][nb][q] = 0.f;

#pragma unroll
        for (int kb = 0; kb < 8; kb++) {
            uint32_t bh[4][2];
#pragma unroll
            for (int nb2 = 0; nb2 < 2; nb2++) {
                uint32_t boff = swz(b_row_main + nb2 * 16, kb * 32 + b_kh * 16);
                uint32_t rr[4];
                ldsm4(rr, sb + B_H_OFF + boff);
                bh[nb2 * 2][0] = rr[0]; bh[nb2 * 2][1] = rr[1];
                bh[nb2 * 2 + 1][0] = rr[2]; bh[nb2 * 2 + 1][1] = rr[3];
            }
#pragma unroll
            for (int mb = 0; mb < 2; mb++) {
                uint32_t aoff = swz(wm * 32 + mb * 16 + a_row, kb * 32 + a_kh * 16);
                uint32_t ahi[4], alo[4];
                ldsm4(ahi, sb + A_HI_OFF + aoff);
                ldsm4(alo, sb + A_LO_OFF + aoff);
#pragma unroll
                for (int nb = 0; nb < 4; nb++) {
                    mma16816(acc[mb][nb], ahi, bh[nb]);
                    mma16816(acc[mb][nb], alo, bh[nb]);
                }
            }
        }

        // ---- phase 5: epilogue silu(D+b2).w3 -> s_part ----
#pragma unroll
        for (int mb = 0; mb < 2; mb++) {
            int h = wm * 2 + mb;
            float p0 = 0.f, p1 = 0.f;
#pragma unroll
            for (int nb = 0; nb < 4; nb++) {
                int c0 = wn * 32 + nb * 8 + tid4 * 2;
                float2 w3v = *(const float2*)(&s_w3T[h * 128 + c0]);
                p0 += silu_t(acc[mb][nb][0] + b2r[nb * 2]) * w3v.x +
                      silu_t(acc[mb][nb][1] + b2r[nb * 2 + 1]) * w3v.y;
                p1 += silu_t(acc[mb][nb][2] + b2r[nb * 2]) * w3v.x +
                      silu_t(acc[mb][nb][3] + b2r[nb * 2 + 1]) * w3v.y;
            }
            p0 += __shfl_xor_sync(0xffffffffu, p0, 1);
            p0 += __shfl_xor_sync(0xffffffffu, p0, 2);
            p1 += __shfl_xor_sync(0xffffffffu, p1, 1);
            p1 += __shfl_xor_sync(0xffffffffu, p1, 2);
            if (tid4 == 0) {
                int m = wm * 32 + mb * 16 + gid;
                atomicAdd(&s_part[m], p0);
                atomicAdd(&s_part[m + 8], p1);
            }
        }
        __syncthreads();

        if (tid < 128) {
            int h = tid >> 4, p = tid & 15;
            int j = j0 + p;
            float s = s_part[tid] + s_ab3[h] + mask[i * N_E + j];
            s = fminf(fmaxf(s, -1e9f), 1e9f);
            g_scores[(h * N_E + i) * N_E + j] = s;
        }
        __syncthreads();
    }
}

// ---------------- kernel 5: softmax + feats + coord partials ----------------
__global__ void k_soft(const float* __restrict__ ec) {
    int i = blockIdx.x, h = blockIdx.y;
    int tid = threadIdx.x, lane = tid & 31, wid = tid >> 5;
    int j = tid;
    __shared__ float s_r[12];
    __shared__ float s_feat[12 * 16];
    __shared__ float s_c[12 * 3];
    __shared__ float s_b;

    float sc = g_scores[(h * N_E + i) * N_E + j];
    float m = wmax(sc);
    if (lane == 0) s_r[wid] = m;
    __syncthreads();
    if (tid == 0) {
        float mm = s_r[0];
        for (int w = 1; w < 12; w++) mm = fmaxf(mm, s_r[w]);
        s_b = mm;
    }
    __syncthreads();
    float e = __expf(sc - s_b);
    float su = wsum(e);
    if (lane == 0) s_r[wid] = su;
    __syncthreads();
    if (tid == 0) {
        float ss = 0.f;
        for (int w = 0; w < 12; w++) ss += s_r[w];
        s_b = ss;
    }
    __syncthreads();
    float attn = __fdividef(e, s_b);

    float part[16];
    const float* vrow = g_v + j * HIDN + h * DHD;
#pragma unroll
    for (int d = 0; d < 16; d++) part[d] = attn * vrow[d];
#pragma unroll
    for (int d = 0; d < 16; d++) part[d] = wsum(part[d]);
    if (lane == 0) {
#pragma unroll
        for (int d = 0; d < 16; d++) s_feat[wid * 16 + d] = part[d];
    }

    float ga = g_gate[i * NHD + h] * attn;
    float cv[3];
    cv[0] = ga * (ec[i * 3 + 0] - ec[j * 3 + 0]);
    cv[1] = ga * (ec[i * 3 + 1] - ec[j * 3 + 1]);
    cv[2] = ga * (ec[i * 3 + 2] - ec[j * 3 + 2]);
#pragma unroll
    for (int d = 0; d < 3; d++) {
        float v = wsum(cv[d]);
        if (lane == 0) s_c[wid * 3 + d] = v;
    }
    __syncthreads();
    if (tid < 16) {
        float a = 0.f;
        for (int w = 0; w < 12; w++) a += s_feat[w * 16 + tid];
        g_upd[i * HIDN + h * DHD + tid] = a;
    }
    if (tid >= 32 && tid < 35) {
        int d = tid - 32;
        float a = 0.f;
        for (int w = 0; w < 12; w++) a += s_c[w * 3 + d];
        g_cpart[(i * NHD + h) * 3 + d] = a;
    }
}

// ---------------- kernel 6: output proj + layernorm + coords ----------------
__global__ void k_out(const float* __restrict__ ef, const float* __restrict__ wo,
                      const float* __restrict__ bo, const float* __restrict__ lng,
                      const float* __restrict__ lnb, const float* __restrict__ ec,
                      float* __restrict__ out) {
    int i = blockIdx.x, t = threadIdx.x, lane = t & 31, wid = t >> 5;
    __shared__ float s_u[HIDN];
    __shared__ float s_r[4];
    __shared__ float s_b;
    s_u[t] = g_upd[i * HIDN + t];
    __syncthreads();
    float acc = ef[i * HIDN + t] + bo[t];
#pragma unroll 4
    for (int c = 0; c < HIDN; c++) acc += s_u[c] * wo[c * HIDN + t];
    float m = wsum(acc);
    if (lane == 0) s_r[wid] = m;
    __syncthreads();
    if (t == 0) s_b = (s_r[0] + s_r[1] + s_r[2] + s_r[3]) * (1.0f / 128.0f);
    __syncthreads();
    float mu = s_b;
    float d = acc - mu;
    float v = wsum(d * d);
    __syncthreads();
    if (lane == 0) s_r[wid] = v;
    __syncthreads();
    if (t == 0) s_b = (s_r[0] + s_r[1] + s_r[2] + s_r[3]) * (1.0f / 128.0f);
    __syncthreads();
    out[i * HIDN + t] = d * rsqrtf(s_b + 1e-5f) * lng[t] + lnb[t];
    if (t < 3) {
        float a = 0.f;
#pragma unroll
        for (int h = 0; h < NHD; h++) a += g_cpart[(i * NHD + h) * 3 + t];
        out[N_E * HIDN + i * 3 + t] = ec[i * 3 + t] + a * 0.125f;
    }
}

// ---------------- launch ----------------
extern "C" void kernel_launch(void* const* d_in, const int* in_sizes, int n_in,
                              void* d_out, int out_size) {
    const float* ef = (const float*)d_in[0];
    const float* ec = (const float*)d_in[1];
    const float* mask = (const float*)d_in[2];
    const float* wq = (const float*)d_in[3];
    const float* wk = (const float*)d_in[4];
    const float* wv = (const float*)d_in[5];
    const float* rc = (const float*)d_in[6];
    const float* rw = (const float*)d_in[7];
    const float* aw1 = (const float*)d_in[8];
    const float* ab1 = (const float*)d_in[9];
    const float* aw2 = (const float*)d_in[10];
    const float* ab2 = (const float*)d_in[11];
    const float* aw3 = (const float*)d_in[12];
    const float* ab3 = (const float*)d_in[13];
    const float* gw1 = (const float*)d_in[14];
    const float* gb1 = (const float*)d_in[15];
    const float* gw2 = (const float*)d_in[16];
    const float* gb2 = (const float*)d_in[17];
    const float* wo = (const float*)d_in[18];
    const float* bo = (const float*)d_in[19];
    const float* lng = (const float*)d_in[20];
    const float* lnb = (const float*)d_in[21];
    float* out = (float*)d_out;

    k_qkv<<<N_E, 128>>>(ef, wq, wk, wv);
    k_qckc<<<dim3(N_E, NHD), 128>>>(aw1);
    k_w2t<<<64, 256>>>(aw2);
    k_w1rb<<<64, 256>>>(aw1, ab1);

    cudaFuncSetAttribute(k_pair, cudaFuncAttributeMaxDynamicSharedMemorySize, K4_SMEM_BYTES);
    k_pair<<<NBLK, 512, K4_SMEM_BYTES>>>(ec, rc, rw, ab2, aw3, ab3, mask);

    k_gate<<<dim3(N_E, NHD), 128>>>(gw1, gb1, gw2, gb2);
    k_soft<<<dim3(N_E, NHD), N_E>>>(ec);
    k_out<<<N_E, 128>>>(ef, wo, bo, lng, lnb, ec, out);
}

// round 12
// speedup vs baseline: 4.7980x; 1.1804x over previous
#include <cuda_runtime.h>
#include <cuda_bf16.h>
#include <cuda_fp16.h>
#include <cstdint>

#define N_E 384
#define HIDN 128
#define NHD 8
#define DHD 16
#define PAIRS 16
#define NJB (N_E / PAIRS)     // 24
#define NTILES (N_E * NJB)    // 9216
#define NBLK 148

typedef unsigned long long ull;

// ---------------- scratch ----------------
__device__ float g_q[N_E * HIDN];
__device__ float g_k[N_E * HIDN];
__device__ float g_v[N_E * HIDN];
__device__ float g_qcT[N_E * HIDN * NHD];  // [i][c][h]
__device__ float g_kcT[N_E * HIDN * NHD];  // [j][c][h]
__device__ float g_gate[N_E * NHD];
__device__ float g_scores[NHD * N_E * N_E];
__device__ float g_upd[N_E * HIDN];
__device__ float g_cpart[N_E * NHD * 3];
__device__ __half g_w2t_h[HIDN * HIDN];   // [cout][cin] fp16
__device__ __half g_w1b_h[HIDN * HIDN];   // [c][k] k: 0..64 rbf/dot, 65 bias

// ---------------- helpers ----------------
__device__ __forceinline__ float silu_f(float x) {
    return __fdividef(x, 1.0f + __expf(-x));
}
__device__ __forceinline__ float silu_t(float x) {  // tanh-based, 1 MUFU
    float hx = 0.5f * x, t;
    asm("tanh.approx.f32 %0, %1;" : "=f"(t) : "f"(hx));
    return fmaf(hx, t, hx);
}
__device__ __forceinline__ float wsum(float v) {
#pragma unroll
    for (int o = 16; o; o >>= 1) v += __shfl_xor_sync(0xffffffffu, v, o);
    return v;
}
__device__ __forceinline__ float wmax(float v) {
#pragma unroll
    for (int o = 16; o; o >>= 1) v = fmaxf(v, __shfl_xor_sync(0xffffffffu, v, o));
    return v;
}
__device__ __forceinline__ uint32_t smem_u32(const void* p) {
    uint32_t a;
    asm("{ .reg .u64 t; cvta.to.shared.u64 t, %1; cvt.u32.u64 %0, t; }" : "=r"(a) : "l"(p));
    return a;
}
// fp16 m16n8k16 HMMA, D += A*B
__device__ __forceinline__ void mma16816(float* c, const uint32_t* a, const uint32_t* b) {
    asm volatile(
        "mma.sync.aligned.m16n8k16.row.col.f32.f16.f16.f32 "
        "{%0,%1,%2,%3}, {%4,%5,%6,%7}, {%8,%9}, {%0,%1,%2,%3};"
        : "+f"(c[0]), "+f"(c[1]), "+f"(c[2]), "+f"(c[3])
        : "r"(a[0]), "r"(a[1]), "r"(a[2]), "r"(a[3]), "r"(b[0]), "r"(b[1]));
}
__device__ __forceinline__ void ldsm4(uint32_t* r, uint32_t addr) {
    asm volatile("ldmatrix.sync.aligned.m8n8.x4.shared.b16 {%0,%1,%2,%3}, [%4];"
                 : "=r"(r[0]), "=r"(r[1]), "=r"(r[2]), "=r"(r[3]) : "r"(addr));
}
__device__ __forceinline__ uint32_t swz(int m, int cbyte) {
    return (uint32_t)(m * 256 + (cbyte ^ ((m & 7) << 4)));
}

// ---------------- kernel 1: q,k,v projections ----------------
__global__ void k_qkv(const float* __restrict__ ef, const float* __restrict__ wq,
                      const float* __restrict__ wk, const float* __restrict__ wv) {
    int i = blockIdx.x, t = threadIdx.x;
    __shared__ float s_e[HIDN];
    s_e[t] = ef[i * HIDN + t];
    __syncthreads();
    float aq = 0.f, ak = 0.f, av = 0.f;
#pragma unroll 4
    for (int c = 0; c < HIDN; c++) {
        float e = s_e[c];
        aq += e * wq[c * HIDN + t];
        ak += e * wk[c * HIDN + t];
        av += e * wv[c * HIDN + t];
    }
    g_q[i * HIDN + t] = aq;
    g_k[i * HIDN + t] = ak;
    g_v[i * HIDN + t] = av;
}

// ---------------- kernel 2: qc/kc (transposed [edge][c][h]) ----------------
__global__ void k_qckc(const float* __restrict__ aw1) {
    int i = blockIdx.x, h = blockIdx.y, t = threadIdx.x;
    const float* qr = g_q + i * HIDN + h * DHD;
    const float* kr = g_k + i * HIDN + h * DHD;
    float aq = 0.f, ak = 0.f;
#pragma unroll
    for (int d = 0; d < DHD; d++) {
        aq += qr[d] * aw1[d * HIDN + t];
        ak += kr[d] * aw1[(DHD + d) * HIDN + t];
    }
    g_qcT[(i * HIDN + t) * NHD + h] = aq;
    g_kcT[(i * HIDN + t) * NHD + h] = ak;
}

// ---------------- kernel 3: gates ----------------
__global__ void k_gate(const float* __restrict__ gw1, const float* __restrict__ gb1,
                       const float* __restrict__ gw2, const float* __restrict__ gb2) {
    int i = blockIdx.x, h = blockIdx.y, t = threadIdx.x;
    int lane = t & 31, wid = t >> 5;
    const float* vr = g_v + i * HIDN + h * DHD;
    float acc = gb1[t];
#pragma unroll
    for (int d = 0; d < DHD; d++) acc += vr[d] * gw1[d * HIDN + t];
    float p = silu_f(acc) * gw2[t];
    p = wsum(p);
    __shared__ float sr[4];
    if (lane == 0) sr[wid] = p;
    __syncthreads();
    if (t == 0) {
        float s = sr[0] + sr[1] + sr[2] + sr[3] + gb2[0];
        g_gate[i * NHD + h] = __fdividef(1.0f, 1.0f + __expf(-s));
    }
}

// ---------------- kernel 3b: w2^T fp16 ----------------
__global__ void k_w2t(const float* __restrict__ aw2) {
    int idx = blockIdx.x * 256 + threadIdx.x;  // 16384
    int cout = idx >> 7, cin = idx & 127;
    g_w2t_h[idx] = __float2half_rn(aw2[cin * HIDN + cout]);
}

// ---------------- kernel 3c: w1 geometric block fp16 [c][k] ----------------
__global__ void k_w1rb(const float* __restrict__ aw1, const float* __restrict__ ab1) {
    int idx = blockIdx.x * 256 + threadIdx.x;  // 16384
    int c = idx >> 7, k = idx & 127;
    float w = 0.f;
    if (k < 65) w = aw1[(32 + k) * HIDN + c];
    else if (k == 65) w = ab1[c];
    g_w1b_h[idx] = __float2half_rn(w);
}

// ---------------- kernel 4: persistent pair-MLP, fp16 1-pass HMMA, 512 thr ----------------
#define A_H_OFF 0           // 32768 [128 m][256B]
#define B_H_OFF 32768       // 32768 w2^T fp16
#define W1B_H_OFF 65536     // 32768 [c][256B]
#define RBF_HI_OFF 98304    // 4096 [16 p][256B]
#define RBF_LO_OFF 102400   // 4096
#define BASE_OFF 106496     // 8192 f32 [16 p][128 c]
#define QCT_OFF 114688      // 4096 f32 [c][h]
#define W3T_OFF 118784      // 4096 f32 [h][c]
#define AB3_OFF 122880      // 32
#define RC_OFF 122912       // 256
#define RW_OFF 123168       // 256
#define SPART_OFF 123424    // 512
#define K4_SMEM_BYTES 123936

__global__ void __launch_bounds__(512, 1)
k_pair(const float* __restrict__ ec, const float* __restrict__ rc,
       const float* __restrict__ rw, const float* __restrict__ ab2,
       const float* __restrict__ aw3, const float* __restrict__ ab3,
       const float* __restrict__ mask) {
    extern __shared__ char sm[];
    const uint32_t sb = smem_u32(sm);
    float* s_base = (float*)(sm + BASE_OFF);
    float* s_qcT = (float*)(sm + QCT_OFF);
    float* s_w3T = (float*)(sm + W3T_OFF);
    float* s_ab3 = (float*)(sm + AB3_OFF);
    float* s_rc = (float*)(sm + RC_OFF);
    float* s_rw = (float*)(sm + RW_OFF);
    float* s_part = (float*)(sm + SPART_OFF);

    int tid = threadIdx.x, lane = tid & 31, warp = tid >> 5;
    int gid = lane >> 2, tid4 = lane & 3;
    int wm = warp >> 2, wn = warp & 3;   // main MMA: M-split 4 x N-split 4
    int cpi = tid & 63, pg2 = tid >> 6;  // silu stage: c2 = 2*cpi, pairs pg2*2..+1
    int c2 = cpi * 2;

    // ---- one-time init ----
    for (int idx = tid; idx < 1024; idx += 512) {
        int h = idx >> 7, c = idx & 127;
        s_w3T[idx] = aw3[c * NHD + h];
    }
    if (tid < 8) s_ab3[tid] = ab3[tid];
    if (tid < 64) {
        s_rc[tid] = rc[tid];
        s_rw[tid] = rw[tid];
    }
    for (int idx = tid; idx < 2048; idx += 512) {
        int n = idx >> 4, k0 = (idx & 15) * 8;
        uint32_t off = swz(n, k0 * 2);
        *(uint4*)(sm + B_H_OFF + off) = *(const uint4*)(g_w2t_h + n * HIDN + k0);
        *(uint4*)(sm + W1B_H_OFF + off) = *(const uint4*)(g_w1b_h + n * HIDN + k0);
    }
    for (int idx = tid; idx < 1024; idx += 512) {
        ((uint32_t*)(sm + RBF_HI_OFF))[idx] = 0;
        ((uint32_t*)(sm + RBF_LO_OFF))[idx] = 0;
    }
    __syncthreads();
    if (tid < 16) {
        *(uint16_t*)(sm + RBF_HI_OFF + swz(tid, 130)) = 0x3C00;  // fp16(1.0)
    }
    float b2r[8];
#pragma unroll
    for (int nb = 0; nb < 4; nb++) {
        int c0 = wn * 32 + nb * 8 + tid4 * 2;
        b2r[nb * 2] = ab2[c0];
        b2r[nb * 2 + 1] = ab2[c0 + 1];
    }
    __syncthreads();

    // ldmatrix lane addressing
    int a_row = lane & 15;
    int a_kh = (lane >> 4) & 1;
    int b_row_main = wn * 32 + ((lane >> 4) & 1) * 8 + (lane & 7);
    int b_row_base = warp * 16 + ((lane >> 4) & 1) * 8 + (lane & 7);  // warps 0-7 only
    int b_kh = (lane >> 3) & 1;

    for (int tile = blockIdx.x; tile < NTILES; tile += NBLK) {
        int i = tile / NJB;
        int j0 = (tile % NJB) * PAIRS;

        // ---- phase 1: rbf + dot; qcT; zero s_part ----
        if (tid < 128) s_part[tid] = 0.f;
        *(float2*)(&s_qcT[tid * 2]) = *(const float2*)(&g_qcT[i * 1024 + tid * 2]);
        float ci0 = ec[i * 3], ci1 = ec[i * 3 + 1], ci2 = ec[i * 3 + 2];
        {
            int p = tid & 15, rq = tid >> 4;  // rq 0..31 -> r = 2rq, 2rq+1
            int j = j0 + p;
            float cj0 = ec[j * 3], cj1 = ec[j * 3 + 1], cj2 = ec[j * 3 + 2];
            float dx = ci0 - cj0, dy = ci1 - cj1, dz = ci2 - cj2;
            float dist = sqrtf(dx * dx + dy * dy + dz * dz) + 1e-8f;
            dist = fminf(fmaxf(dist, 1e-8f), 1e8f);
            int r0 = rq * 2, r1 = r0 + 1;
            float d0 = dist - s_rc[r0], d1 = dist - s_rc[r1];
            float v0 = (dist <= 10.0f) ? __expf(-s_rw[r0] * d0 * d0) : 0.0f;
            float v1 = (dist <= 10.0f) ? __expf(-s_rw[r1] * d1 * d1) : 0.0f;
            __half2 hh = __floats2half2_rn(v0, v1);
            float e0 = v0 - __half2float(__low2half(hh));
            float e1 = v1 - __half2float(__high2half(hh));
            __half2 ll = __floats2half2_rn(e0, e1);
            uint32_t off = swz(p, rq * 4);
            *(uint32_t*)(sm + RBF_HI_OFF + off) = *(uint32_t*)&hh;
            *(uint32_t*)(sm + RBF_LO_OFF + off) = *(uint32_t*)&ll;
        }
        if (tid < 16) {
            int j = j0 + tid;
            float cj0 = ec[j * 3], cj1 = ec[j * 3 + 1], cj2 = ec[j * 3 + 2];
            float dot = ci0 * cj0 + ci1 * cj1 + ci2 * cj2;
            dot = fminf(fmaxf(dot, -1e8f), 1e8f);
            __half dh = __float2half_rn(dot);
            __half dl = __float2half_rn(dot - __half2float(dh));
            uint32_t off = swz(tid, 128);
            *(uint16_t*)(sm + RBF_HI_OFF + off) = *(uint16_t*)&dh;
            *(uint16_t*)(sm + RBF_LO_OFF + off) = *(uint16_t*)&dl;
        }

        // kc prefetch for phase 3 (latency overlapped with phase 2 GEMM)
        float kcA[16], kcB[16];
        {
            const float* kcp0 = g_kcT + ((j0 + pg2 * 2) * HIDN + c2) * 8;
            const float* kcp1 = g_kcT + ((j0 + pg2 * 2 + 1) * HIDN + c2) * 8;
            *(float4*)(kcA) = *(const float4*)(kcp0);
            *(float4*)(kcA + 4) = *(const float4*)(kcp0 + 4);
            *(float4*)(kcA + 8) = *(const float4*)(kcp0 + 8);
            *(float4*)(kcA + 12) = *(const float4*)(kcp0 + 12);
            *(float4*)(kcB) = *(const float4*)(kcp1);
            *(float4*)(kcB + 4) = *(const float4*)(kcp1 + 4);
            *(float4*)(kcB + 8) = *(const float4*)(kcp1 + 8);
            *(float4*)(kcB + 12) = *(const float4*)(kcp1 + 12);
        }
        __syncthreads();

        // ---- phase 2: base GEMM (16 x 128, K eff 66), 2-pass; warps 0-7 ----
        if (warp < 8) {
            float bacc[2][4];
#pragma unroll
            for (int nb = 0; nb < 2; nb++)
#pragma unroll
                for (int q = 0; q < 4; q++) bacc[nb][q] = 0.f;
#pragma unroll
            for (int kb = 0; kb < 5; kb++) {
                uint32_t rhi[4], rlo[4];
                ldsm4(rhi, sb + RBF_HI_OFF + swz(a_row, kb * 32 + a_kh * 16));
                ldsm4(rlo, sb + RBF_LO_OFF + swz(a_row, kb * 32 + a_kh * 16));
                uint32_t boff = swz(b_row_base, kb * 32 + b_kh * 16);
                uint32_t rr[4];
                uint32_t wh[2][2];
                ldsm4(rr, sb + W1B_H_OFF + boff);
                wh[0][0] = rr[0]; wh[0][1] = rr[1]; wh[1][0] = rr[2]; wh[1][1] = rr[3];
#pragma unroll
                for (int nb = 0; nb < 2; nb++) {
                    mma16816(bacc[nb], rhi, wh[nb]);
                    mma16816(bacc[nb], rlo, wh[nb]);
                }
            }
#pragma unroll
            for (int nb = 0; nb < 2; nb++) {
                int c0 = warp * 16 + nb * 8 + tid4 * 2;
                float2 v0 = {bacc[nb][0], bacc[nb][1]};
                float2 v1 = {bacc[nb][2], bacc[nb][3]};
                *(float2*)(&s_base[gid * 128 + c0]) = v0;
                *(float2*)(&s_base[(gid + 8) * 128 + c0]) = v1;
            }
        }
        __syncthreads();

        // ---- phase 3: x1 = silu(base + qc + kc) -> A (fp16, 1-pass) ----
        {
            float qv0[8], qv1[8];
            *(float4*)(qv0) = *(const float4*)(&s_qcT[c2 * 8]);
            *(float4*)(qv0 + 4) = *(const float4*)(&s_qcT[c2 * 8 + 4]);
            *(float4*)(qv1) = *(const float4*)(&s_qcT[c2 * 8 + 8]);
            *(float4*)(qv1 + 4) = *(const float4*)(&s_qcT[c2 * 8 + 12]);
#pragma unroll
            for (int pp = 0; pp < 2; pp++) {
                int p = pg2 * 2 + pp;
                float2 bs = *(const float2*)(&s_base[p * 128 + c2]);
                const float* kc = pp ? kcB : kcA;
#pragma unroll
                for (int h = 0; h < NHD; h++) {
                    float x0 = silu_t(bs.x + qv0[h] + kc[h]);
                    float x1 = silu_t(bs.y + qv1[h] + kc[h + 8]);
                    __half2 hh = __floats2half2_rn(x0, x1);
                    int m = h * PAIRS + p;
                    uint32_t off = swz(m, c2 * 2);
                    *(uint32_t*)(sm + A_H_OFF + off) = *(uint32_t*)&hh;
                }
            }
        }
        __syncthreads();

        // ---- phase 4: main GEMM D = A * Bh (1-pass fp16) ----
        float acc[2][4][4];
#pragma unroll
        for (int mb = 0; mb < 2; mb++)
#pragma unroll
            for (int nb = 0; nb < 4; nb++)
#pragma unroll
                for (int q = 0; q < 4; q++) acc[mb][nb][q] = 0.f;

#pragma unroll
        for (int kb = 0; kb < 8; kb++) {
            uint32_t bh[4][2];
#pragma unroll
            for (int nb2 = 0; nb2 < 2; nb2++) {
                uint32_t boff = swz(b_row_main + nb2 * 16, kb * 32 + b_kh * 16);
                uint32_t rr[4];
                ldsm4(rr, sb + B_H_OFF + boff);
                bh[nb2 * 2][0] = rr[0]; bh[nb2 * 2][1] = rr[1];
                bh[nb2 * 2 + 1][0] = rr[2]; bh[nb2 * 2 + 1][1] = rr[3];
            }
#pragma unroll
            for (int mb = 0; mb < 2; mb++) {
                uint32_t aoff = swz(wm * 32 + mb * 16 + a_row, kb * 32 + a_kh * 16);
                uint32_t ahi[4];
                ldsm4(ahi, sb + A_H_OFF + aoff);
#pragma unroll
                for (int nb = 0; nb < 4; nb++) {
                    mma16816(acc[mb][nb], ahi, bh[nb]);
                }
            }
        }

        // ---- phase 5: epilogue silu(D+b2).w3 -> s_part ----
#pragma unroll
        for (int mb = 0; mb < 2; mb++) {
            int h = wm * 2 + mb;
            float p0 = 0.f, p1 = 0.f;
#pragma unroll
            for (int nb = 0; nb < 4; nb++) {
                int c0 = wn * 32 + nb * 8 + tid4 * 2;
                float2 w3v = *(const float2*)(&s_w3T[h * 128 + c0]);
                p0 += silu_t(acc[mb][nb][0] + b2r[nb * 2]) * w3v.x +
                      silu_t(acc[mb][nb][1] + b2r[nb * 2 + 1]) * w3v.y;
                p1 += silu_t(acc[mb][nb][2] + b2r[nb * 2]) * w3v.x +
                      silu_t(acc[mb][nb][3] + b2r[nb * 2 + 1]) * w3v.y;
            }
            p0 += __shfl_xor_sync(0xffffffffu, p0, 1);
            p0 += __shfl_xor_sync(0xffffffffu, p0, 2);
            p1 += __shfl_xor_sync(0xffffffffu, p1, 1);
            p1 += __shfl_xor_sync(0xffffffffu, p1, 2);
            if (tid4 == 0) {
                int m = wm * 32 + mb * 16 + gid;
                atomicAdd(&s_part[m], p0);
                atomicAdd(&s_part[m + 8], p1);
            }
        }
        __syncthreads();

        if (tid < 128) {
            int h = tid >> 4, p = tid & 15;
            int j = j0 + p;
            float s = s_part[tid] + s_ab3[h] + mask[i * N_E + j];
            s = fminf(fmaxf(s, -1e9f), 1e9f);
            g_scores[(h * N_E + i) * N_E + j] = s;
        }
        __syncthreads();
    }
}

// ---------------- kernel 5: softmax + feats + coord partials ----------------
__global__ void k_soft(const float* __restrict__ ec) {
    int i = blockIdx.x, h = blockIdx.y;
    int tid = threadIdx.x, lane = tid & 31, wid = tid >> 5;
    int j = tid;
    __shared__ float s_r[12];
    __shared__ float s_feat[12 * 16];
    __shared__ float s_c[12 * 3];
    __shared__ float s_b;

    float sc = g_scores[(h * N_E + i) * N_E + j];
    float m = wmax(sc);
    if (lane == 0) s_r[wid] = m;
    __syncthreads();
    if (tid == 0) {
        float mm = s_r[0];
        for (int w = 1; w < 12; w++) mm = fmaxf(mm, s_r[w]);
        s_b = mm;
    }
    __syncthreads();
    float e = __expf(sc - s_b);
    float su = wsum(e);
    if (lane == 0) s_r[wid] = su;
    __syncthreads();
    if (tid == 0) {
        float ss = 0.f;
        for (int w = 0; w < 12; w++) ss += s_r[w];
        s_b = ss;
    }
    __syncthreads();
    float attn = __fdividef(e, s_b);

    float part[16];
    const float* vrow = g_v + j * HIDN + h * DHD;
#pragma unroll
    for (int d = 0; d < 16; d++) part[d] = attn * vrow[d];
#pragma unroll
    for (int d = 0; d < 16; d++) part[d] = wsum(part[d]);
    if (lane == 0) {
#pragma unroll
        for (int d = 0; d < 16; d++) s_feat[wid * 16 + d] = part[d];
    }

    float ga = g_gate[i * NHD + h] * attn;
    float cv[3];
    cv[0] = ga * (ec[i * 3 + 0] - ec[j * 3 + 0]);
    cv[1] = ga * (ec[i * 3 + 1] - ec[j * 3 + 1]);
    cv[2] = ga * (ec[i * 3 + 2] - ec[j * 3 + 2]);
#pragma unroll
    for (int d = 0; d < 3; d++) {
        float v = wsum(cv[d]);
        if (lane == 0) s_c[wid * 3 + d] = v;
    }
    __syncthreads();
    if (tid < 16) {
        float a = 0.f;
        for (int w = 0; w < 12; w++) a += s_feat[w * 16 + tid];
        g_upd[i * HIDN + h * DHD + tid] = a;
    }
    if (tid >= 32 && tid < 35) {
        int d = tid - 32;
        float a = 0.f;
        for (int w = 0; w < 12; w++) a += s_c[w * 3 + d];
        g_cpart[(i * NHD + h) * 3 + d] = a;
    }
}

// ---------------- kernel 6: output proj + layernorm + coords ----------------
__global__ void k_out(const float* __restrict__ ef, const float* __restrict__ wo,
                      const float* __restrict__ bo, const float* __restrict__ lng,
                      const float* __restrict__ lnb, const float* __restrict__ ec,
                      float* __restrict__ out) {
    int i = blockIdx.x, t = threadIdx.x, lane = t & 31, wid = t >> 5;
    __shared__ float s_u[HIDN];
    __shared__ float s_r[4];
    __shared__ float s_b;
    s_u[t] = g_upd[i * HIDN + t];
    __syncthreads();
    float acc = ef[i * HIDN + t] + bo[t];
#pragma unroll 4
    for (int c = 0; c < HIDN; c++) acc += s_u[c] * wo[c * HIDN + t];
    float m = wsum(acc);
    if (lane == 0) s_r[wid] = m;
    __syncthreads();
    if (t == 0) s_b = (s_r[0] + s_r[1] + s_r[2] + s_r[3]) * (1.0f / 128.0f);
    __syncthreads();
    float mu = s_b;
    float d = acc - mu;
    float v = wsum(d * d);
    __syncthreads();
    if (lane == 0) s_r[wid] = v;
    __syncthreads();
    if (t == 0) s_b = (s_r[0] + s_r[1] + s_r[2] + s_r[3]) * (1.0f / 128.0f);
    __syncthreads();
    out[i * HIDN + t] = d * rsqrtf(s_b + 1e-5f) * lng[t] + lnb[t];
    if (t < 3) {
        float a = 0.f;
#pragma unroll
        for (int h = 0; h < NHD; h++) a += g_cpart[(i * NHD + h) * 3 + t];
        out[N_E * HIDN + i * 3 + t] = ec[i * 3 + t] + a * 0.125f;
    }
}

// ---------------- launch ----------------
extern "C" void kernel_launch(void* const* d_in, const int* in_sizes, int n_in,
                              void* d_out, int out_size) {
    const float* ef = (const float*)d_in[0];
    const float* ec = (const float*)d_in[1];
    const float* mask = (const float*)d_in[2];
    const float* wq = (const float*)d_in[3];
    const float* wk = (const float*)d_in[4];
    const float* wv = (const float*)d_in[5];
    const float* rc = (const float*)d_in[6];
    const float* rw = (const float*)d_in[7];
    const float* aw1 = (const float*)d_in[8];
    const float* ab1 = (const float*)d_in[9];
    const float* aw2 = (const float*)d_in[10];
    const float* ab2 = (const float*)d_in[11];
    const float* aw3 = (const float*)d_in[12];
    const float* ab3 = (const float*)d_in[13];
    const float* gw1 = (const float*)d_in[14];
    const float* gb1 = (const float*)d_in[15];
    const float* gw2 = (const float*)d_in[16];
    const float* gb2 = (const float*)d_in[17];
    const float* wo = (const float*)d_in[18];
    const float* bo = (const float*)d_in[19];
    const float* lng = (const float*)d_in[20];
    const float* lnb = (const float*)d_in[21];
    float* out = (float*)d_out;

    k_qkv<<<N_E, 128>>>(ef, wq, wk, wv);
    k_qckc<<<dim3(N_E, NHD), 128>>>(aw1);
    k_w2t<<<64, 256>>>(aw2);
    k_w1rb<<<64, 256>>>(aw1, ab1);

    cudaFuncSetAttribute(k_pair, cudaFuncAttributeMaxDynamicSharedMemorySize, K4_SMEM_BYTES);
    k_pair<<<NBLK, 512, K4_SMEM_BYTES>>>(ec, rc, rw, ab2, aw3, ab3, mask);

    k_gate<<<dim3(N_E, NHD), 128>>>(gw1, gb1, gw2, gb2);
    k_soft<<<dim3(N_E, NHD), N_E>>>(ec);
    k_out<<<N_E, 128>>>(ef, wo, bo, lng, lnb, ec, out);
}